// round 5
// baseline (speedup 1.0000x reference)
#include <cuda_runtime.h>
#include <math.h>

#define TT   1024
#define BB   32
#define CC   1024
#define KWW  3
#define NC   16      // t-chunks in fused pass
#define TC   64      // t per chunk (NC*TC == TT)

// ---------------- scratch ----------------
__device__ __align__(16) float g_saq[BB * CC];          // sa(q1) [b][c]
__device__ __align__(16) float g_ker[BB * KWW * CC];    // kernels [b][w][c]
__device__ __align__(16) float g_pm[BB * NC * 4];       // per chunk: m1,m2,ws1,ws2
__device__ __align__(16) float g_pacc1[BB * NC * CC];   // chunk partial acc path1
__device__ __align__(16) float g_pacc2[BB * NC * CC];   // chunk partial acc path2

__device__ __forceinline__ float tanh_approx(float x) {
    float y;
    asm("tanh.approx.f32 %0, %1;" : "=f"(y) : "f"(x));
    return y;
}

// ============ kernel 1: row GEMMs (transpose fused via smem staging) ============
// 64 blocks x 256 thr. Block handles 64 output rows; warp w -> 8 rows; lane = b.
// Blocks 0..15  : rows 0..1023  of sa_w  (source q1) -> g_saq[b][r]
// Blocks 16..63 : rows 0..3071  of qk_w  (source q2) -> g_ker[b][w][c]
__global__ void __launch_bounds__(256) k_rowgemm(
    const float* __restrict__ q1, const float* __restrict__ q2,
    const float* __restrict__ sa_w, const float* __restrict__ sa_b,
    const float* __restrict__ qk_w, const float* __restrict__ qk_b) {
    __shared__ float qs[128][33];   // padded: conflict-free stores

    int tid  = threadIdx.x;
    int warp = tid >> 5;
    int lane = tid & 31;

    bool is_sa = blockIdx.x < 16;
    int row0 = is_sa ? blockIdx.x * 64 : (blockIdx.x - 16) * 64;   // row within its W
    const float* W  = is_sa ? sa_w : qk_w;
    const float* Bi = is_sa ? sa_b : qk_b;
    const float* q  = is_sa ? q1 : q2;

    int myrow = row0 + warp * 8;    // 8 rows: myrow .. myrow+7

    float acc[8];
#pragma unroll
    for (int j = 0; j < 8; j++) acc[j] = 0.f;

    int sb = tid >> 3;        // b for staging (0..31)
    int sj = tid & 7;         // float4 slot

    for (int kc = 0; kc < 8; kc++) {
        int k0 = kc * 128;
        // stage q[b][k0 .. k0+127] -> qs[k_local][b]
#pragma unroll
        for (int it = 0; it < 4; it++) {
            int k4 = sj + it * 8;                       // float4 index 0..31
            float4 v = *(const float4*)(q + sb * CC + k0 + k4 * 4);
            qs[k4 * 4 + 0][sb] = v.x;
            qs[k4 * 4 + 1][sb] = v.y;
            qs[k4 * 4 + 2][sb] = v.z;
            qs[k4 * 4 + 3][sb] = v.w;
        }
        __syncthreads();

#pragma unroll 4
        for (int k4 = 0; k4 < 32; k4++) {
            float qv0 = qs[k4 * 4 + 0][lane];
            float qv1 = qs[k4 * 4 + 1][lane];
            float qv2 = qs[k4 * 4 + 2][lane];
            float qv3 = qs[k4 * 4 + 3][lane];
#pragma unroll
            for (int j = 0; j < 8; j++) {
                float4 wv = *(const float4*)(W + (size_t)(myrow + j) * CC + k0 + k4 * 4);
                acc[j] = fmaf(wv.x, qv0, acc[j]);
                acc[j] = fmaf(wv.y, qv1, acc[j]);
                acc[j] = fmaf(wv.z, qv2, acc[j]);
                acc[j] = fmaf(wv.w, qv3, acc[j]);
            }
        }
        __syncthreads();
    }

#pragma unroll
    for (int j = 0; j < 8; j++) {
        int r = myrow + j;
        float v = acc[j] + Bi[r];
        if (is_sa) {
            g_saq[lane * CC + r] = v;
        } else {
            int c = r / KWW;
            int w = r - c * KWW;
            g_ker[(lane * KWW + w) * CC + c] = v;
        }
    }
}

// ---------------- dual block reduction (shuffle + one smem stage) ----------------
__device__ __forceinline__ void bred2(float& v1, float& v2, float* sm, int sum_mode) {
    int lane = threadIdx.x & 31;
    int warp = threadIdx.x >> 5;
#pragma unroll
    for (int o = 16; o > 0; o >>= 1) {
        float o1 = __shfl_xor_sync(0xffffffffu, v1, o);
        float o2 = __shfl_xor_sync(0xffffffffu, v2, o);
        if (sum_mode) { v1 += o1; v2 += o2; }
        else          { v1 = fmaxf(v1, o1); v2 = fmaxf(v2, o2); }
    }
    if (lane == 0) { sm[warp] = v1; sm[8 + warp] = v2; }
    __syncthreads();
    float a = sm[lane & 7], b = sm[8 + (lane & 7)];
#pragma unroll
    for (int o = 4; o > 0; o >>= 1) {
        float oa = __shfl_xor_sync(0xffffffffu, a, o);
        float ob = __shfl_xor_sync(0xffffffffu, b, o);
        if (sum_mode) { a += oa; b += ob; }
        else          { a = fmaxf(a, oa); b = fmaxf(b, ob); }
    }
    v1 = __shfl_sync(0xffffffffu, a, 0);
    v2 = __shfl_sync(0xffffffffu, b, 0);
    __syncthreads();
}

// ============ kernel 2: fused flash pass (streams k1,k2 then v1,v2) ============
// grid = BB*NC blocks of 256. Block (b, chunk c): 64 t-rows.
// Phase A: logits a1[t], a2[t] (conv via taps; boundary rows handled in-block).
// Chunk softmax stats (m, ws) + raw weights. Phase B: weighted v accumulation.
__global__ void __launch_bounds__(256) k_fused(
    const float* __restrict__ k1, const float* __restrict__ k2,
    const float* __restrict__ v1, const float* __restrict__ v2,
    const float* __restrict__ a1w, const float* __restrict__ k_mask) {
    __shared__ __align__(16) float s_sq[CC], s_aw[CC], s_r0[CC], s_r1[CC], s_r2[CC];
    __shared__ float sA1[TC], sS0[TC], sS1[TC], sS2[TC], sW1[TC], sW2[TC];
    __shared__ float sEdge[2];
    __shared__ float sm[16];

    int bid = blockIdx.x;
    int b  = bid >> 4;           // / NC
    int c  = bid & (NC - 1);
    int t0 = c * TC;
    int tid = threadIdx.x;
    int warp = tid >> 5;
    int lane = tid & 31;

    {   // stage side data (CC/4 == 256 == blockDim)
        int i = tid;
        ((float4*)s_sq)[i] = ((const float4*)(g_saq + b * CC))[i];
        ((float4*)s_aw)[i] = ((const float4*)a1w)[i];
        ((float4*)s_r0)[i] = ((const float4*)(g_ker + (b * KWW + 0) * CC))[i];
        ((float4*)s_r1)[i] = ((const float4*)(g_ker + (b * KWW + 1) * CC))[i];
        ((float4*)s_r2)[i] = ((const float4*)(g_ker + (b * KWW + 2) * CC))[i];
    }
    __syncthreads();

    // ---- Phase A: per-row logits (warp per t) ----
#pragma unroll
    for (int it = 0; it < TC / 8; ++it) {
        int i = it * 8 + warp;
        int t = t0 + i;
        const float4* k1p = (const float4*)(k1 + (size_t)(t * BB + b) * CC);
        const float4* k2p = (const float4*)(k2 + (size_t)(t * BB + b) * CC);

        float a1 = 0.f, s0 = 0.f, s1 = 0.f, s2 = 0.f;
#pragma unroll
        for (int q = 0; q < 8; q++) {
            int c4 = q * 32 + lane;
            float4 x1 = k1p[c4];
            float4 x2 = k2p[c4];
            float4 sv = ((const float4*)s_sq)[c4];
            float4 av = ((const float4*)s_aw)[c4];
            float4 r0 = ((const float4*)s_r0)[c4];
            float4 r1 = ((const float4*)s_r1)[c4];
            float4 r2 = ((const float4*)s_r2)[c4];

            a1 = fmaf(tanh_approx(sv.x + x1.x), av.x, a1);
            a1 = fmaf(tanh_approx(sv.y + x1.y), av.y, a1);
            a1 = fmaf(tanh_approx(sv.z + x1.z), av.z, a1);
            a1 = fmaf(tanh_approx(sv.w + x1.w), av.w, a1);

            s0 = fmaf(r0.x, x2.x, s0); s0 = fmaf(r0.y, x2.y, s0);
            s0 = fmaf(r0.z, x2.z, s0); s0 = fmaf(r0.w, x2.w, s0);
            s1 = fmaf(r1.x, x2.x, s1); s1 = fmaf(r1.y, x2.y, s1);
            s1 = fmaf(r1.z, x2.z, s1); s1 = fmaf(r1.w, x2.w, s1);
            s2 = fmaf(r2.x, x2.x, s2); s2 = fmaf(r2.y, x2.y, s2);
            s2 = fmaf(r2.z, x2.z, s2); s2 = fmaf(r2.w, x2.w, s2);
        }
#pragma unroll
        for (int o = 16; o > 0; o >>= 1) {
            a1 += __shfl_xor_sync(0xffffffffu, a1, o);
            s0 += __shfl_xor_sync(0xffffffffu, s0, o);
            s1 += __shfl_xor_sync(0xffffffffu, s1, o);
            s2 += __shfl_xor_sync(0xffffffffu, s2, o);
        }
        if (lane == 0) { sA1[i] = a1; sS0[i] = s0; sS1[i] = s1; sS2[i] = s2; }
    }

    // boundary rows: s0 of t0-1 (warp 0), s2 of t0+TC (warp 1)
    if (warp == 0) {
        float s = 0.f;
        if (t0 > 0) {
            const float4* kp = (const float4*)(k2 + (size_t)((t0 - 1) * BB + b) * CC);
#pragma unroll
            for (int q = 0; q < 8; q++) {
                int c4 = q * 32 + lane;
                float4 x = kp[c4];
                float4 r = ((const float4*)s_r0)[c4];
                s += r.x * x.x + r.y * x.y + r.z * x.z + r.w * x.w;
            }
        }
#pragma unroll
        for (int o = 16; o > 0; o >>= 1) s += __shfl_xor_sync(0xffffffffu, s, o);
        if (lane == 0) sEdge[0] = s;
    } else if (warp == 1) {
        float s = 0.f;
        if (t0 + TC < TT) {
            const float4* kp = (const float4*)(k2 + (size_t)((t0 + TC) * BB + b) * CC);
#pragma unroll
            for (int q = 0; q < 8; q++) {
                int c4 = q * 32 + lane;
                float4 x = kp[c4];
                float4 r = ((const float4*)s_r2)[c4];
                s += r.x * x.x + r.y * x.y + r.z * x.z + r.w * x.w;
            }
        }
#pragma unroll
        for (int o = 16; o > 0; o >>= 1) s += __shfl_xor_sync(0xffffffffu, s, o);
        if (lane == 0) sEdge[1] = s;
    }
    __syncthreads();

    // ---- chunk softmax stats ----
    float a1v = -3.0e38f, a2v = -3.0e38f, mk = 0.f;
    if (tid < TC) {
        int i = tid;
        a1v = sA1[i];
        a2v = sS1[i]
            + (i > 0      ? sS0[i - 1] : sEdge[0])
            + (i < TC - 1 ? sS2[i + 1] : sEdge[1]);
        mk = k_mask[(t0 + i) * BB + b];
    }
    float m1 = a1v, m2 = a2v;
    bred2(m1, m2, sm, 0);

    float w1 = 0.f, w2 = 0.f;
    if (tid < TC) {
        w1 = expf(a1v - m1) * mk;
        w2 = expf(a2v - m2) * mk;
        sW1[tid] = w1;
        sW2[tid] = w2;
    }
    float ws1 = w1, ws2 = w2;
    bred2(ws1, ws2, sm, 1);

    if (tid == 0) {
        float4 pm = make_float4(m1, m2, ws1, ws2);
        *(float4*)(g_pm + bid * 4) = pm;
    }
    __syncthreads();

    // ---- Phase B: weighted v accumulation (thread owns float4 feature slice) ----
    float4 A1 = make_float4(0.f, 0.f, 0.f, 0.f);
    float4 A2 = make_float4(0.f, 0.f, 0.f, 0.f);
#pragma unroll 4
    for (int i = 0; i < TC; i++) {
        int t = t0 + i;
        float4 xa = ((const float4*)v1)[(size_t)(t * BB + b) * (CC / 4) + tid];
        float4 xb = ((const float4*)v2)[(size_t)(t * BB + b) * (CC / 4) + tid];
        float u1 = sW1[i];
        float u2 = sW2[i];
        A1.x = fmaf(u1, xa.x, A1.x); A1.y = fmaf(u1, xa.y, A1.y);
        A1.z = fmaf(u1, xa.z, A1.z); A1.w = fmaf(u1, xa.w, A1.w);
        A2.x = fmaf(u2, xb.x, A2.x); A2.y = fmaf(u2, xb.y, A2.y);
        A2.z = fmaf(u2, xb.z, A2.z); A2.w = fmaf(u2, xb.w, A2.w);
    }
    ((float4*)g_pacc1)[bid * (CC / 4) + tid] = A1;
    ((float4*)g_pacc2)[bid * (CC / 4) + tid] = A2;
}

// ============ kernel 3: combine chunks + LayerNorm ============
__device__ __forceinline__ float bred1(float v, float* sm) {
    int lane = threadIdx.x & 31;
    int warp = threadIdx.x >> 5;
#pragma unroll
    for (int o = 16; o > 0; o >>= 1) v += __shfl_xor_sync(0xffffffffu, v, o);
    if (lane == 0) sm[warp] = v;
    __syncthreads();
    float a = sm[lane & 7];
#pragma unroll
    for (int o = 4; o > 0; o >>= 1) a += __shfl_xor_sync(0xffffffffu, a, o);
    a = __shfl_sync(0xffffffffu, a, 0);
    __syncthreads();
    return a;
}

__global__ void __launch_bounds__(256) k_combine(
    const float* __restrict__ ln_g, const float* __restrict__ ln_b,
    float* __restrict__ out) {
    __shared__ float sm[8];
    int b = blockIdx.x;
    int tid = threadIdx.x;

    float m1c[NC], m2c[NC], s1c[NC], s2c[NC];
    float M1 = -3.0e38f, M2 = -3.0e38f;
#pragma unroll
    for (int c = 0; c < NC; c++) {
        float4 pm = *(const float4*)(g_pm + (b * NC + c) * 4);
        m1c[c] = pm.x; m2c[c] = pm.y; s1c[c] = pm.z; s2c[c] = pm.w;
        M1 = fmaxf(M1, pm.x);
        M2 = fmaxf(M2, pm.y);
    }
    float S1 = 0.f, S2 = 0.f;
    float f1[NC], f2[NC];
#pragma unroll
    for (int c = 0; c < NC; c++) {
        f1[c] = expf(m1c[c] - M1);
        f2[c] = expf(m2c[c] - M2);
        S1 += s1c[c] * f1[c];
        S2 += s2c[c] * f2[c];
    }
    float i1 = 1.f / S1, i2 = 1.f / S2;

    float4 x = make_float4(0.f, 0.f, 0.f, 0.f);
#pragma unroll
    for (int c = 0; c < NC; c++) {
        float g1 = f1[c] * i1;
        float g2 = f2[c] * i2;
        float4 p1 = ((const float4*)g_pacc1)[(b * NC + c) * (CC / 4) + tid];
        float4 p2 = ((const float4*)g_pacc2)[(b * NC + c) * (CC / 4) + tid];
        x.x += g1 * p1.x + g2 * p2.x;
        x.y += g1 * p1.y + g2 * p2.y;
        x.z += g1 * p1.z + g2 * p2.z;
        x.w += g1 * p1.w + g2 * p2.w;
    }

    float s = x.x + x.y + x.z + x.w;
    float total = bred1(s, sm);
    float mu = total * (1.f / (float)CC);

    float dx0 = x.x - mu, dx1 = x.y - mu, dx2 = x.z - mu, dx3 = x.w - mu;
    float sq = dx0 * dx0 + dx1 * dx1 + dx2 * dx2 + dx3 * dx3;
    float tot2 = bred1(sq, sm);
    float inv = rsqrtf(tot2 * (1.f / (float)CC) + 1e-6f);

    int d = tid * 4;
    float4 g = *(const float4*)(ln_g + d);
    float4 bb = *(const float4*)(ln_b + d);
    float4 o;
    o.x = dx0 * inv * g.x + bb.x;
    o.y = dx1 * inv * g.y + bb.y;
    o.z = dx2 * inv * g.z + bb.z;
    o.w = dx3 * inv * g.w + bb.w;
    *(float4*)(out + b * CC + d) = o;
}

// ---------------- launch ----------------
extern "C" void kernel_launch(void* const* d_in, const int* in_sizes, int n_in,
                              void* d_out, int out_size) {
    const float* q1     = (const float*)d_in[0];
    const float* k1     = (const float*)d_in[1];
    const float* v1     = (const float*)d_in[2];
    const float* q2     = (const float*)d_in[3];
    const float* k2     = (const float*)d_in[4];
    const float* v2     = (const float*)d_in[5];
    const float* k_mask = (const float*)d_in[6];
    const float* sa_w   = (const float*)d_in[7];
    const float* sa_b   = (const float*)d_in[8];
    const float* a1_w   = (const float*)d_in[9];
    // d_in[10] = a1_b : constant shift, cancels in softmax — unused
    const float* qk_w   = (const float*)d_in[11];
    const float* qk_b   = (const float*)d_in[12];
    const float* ln_g   = (const float*)d_in[13];
    const float* ln_b   = (const float*)d_in[14];
    float* out = (float*)d_out;

    k_rowgemm<<<64, 256>>>(q1, q2, sa_w, sa_b, qk_w, qk_b);
    k_fused<<<BB * NC, 256>>>(k1, k2, v1, v2, a1_w, k_mask);
    k_combine<<<BB, 256>>>(ln_g, ln_b, out);
}

// round 6
// speedup vs baseline: 1.4007x; 1.4007x over previous
#include <cuda_runtime.h>
#include <math.h>

#define TT   1024
#define BB   32
#define CC   1024
#define KWW  3
#define NC   32      // t-chunks in fused pass
#define TC   32      // t per chunk (NC*TC == TT)

// ---------------- scratch ----------------
__device__ __align__(16) float g_saq[BB * CC];          // sa(q1) [b][c]
__device__ __align__(16) float g_ker[BB * KWW * CC];    // kernels [b][w][c]
__device__ __align__(16) float g_pm[BB * NC * 4];       // per chunk: m1,m2,ws1,ws2
__device__ __align__(16) float g_pacc1[BB * NC * CC];   // chunk partial acc path1
__device__ __align__(16) float g_pacc2[BB * NC * CC];   // chunk partial acc path2

__device__ __forceinline__ float tanh_approx(float x) {
    float y;
    asm("tanh.approx.f32 %0, %1;" : "=f"(y) : "f"(x));
    return y;
}

// ============ kernel 1: row GEMMs ============
// 128 blocks x 256 thr. Block = 32 rows. Warp = 4 rows, lane = b.
// Blocks 0..31: sa_w rows (q1) -> g_saq. Blocks 32..127: qk_w rows (q2) -> g_ker.
// q chunk (256 k) staged in smem as float4 [k4][b] -> conflict-free LDS.128.
__global__ void __launch_bounds__(256) k_rowgemm(
    const float* __restrict__ q1, const float* __restrict__ q2,
    const float* __restrict__ sa_w, const float* __restrict__ sa_b,
    const float* __restrict__ qk_w, const float* __restrict__ qk_b) {
    __shared__ __align__(16) float4 qs4[64 * 32];   // [k4][b], 32 KB

    int tid  = threadIdx.x;
    int warp = tid >> 5;
    int lane = tid & 31;

    bool is_sa = blockIdx.x < 32;
    int row0 = (is_sa ? blockIdx.x : blockIdx.x - 32) * 32;
    const float* W  = is_sa ? sa_w : qk_w;
    const float* Bi = is_sa ? sa_b : qk_b;
    const float* q  = is_sa ? q1 : q2;

    int r = row0 + warp * 4;       // 4 rows: r .. r+3

    float acc0 = 0.f, acc1 = 0.f, acc2 = 0.f, acc3 = 0.f;

    int sb = tid >> 3;             // staging b (0..31)
    int sj = tid & 7;

    for (int chunk = 0; chunk < 4; chunk++) {
        int k0 = chunk * 256;
        __syncthreads();
#pragma unroll
        for (int i = 0; i < 8; i++) {
            int k4 = i * 8 + sj;   // 0..63
            qs4[k4 * 32 + sb] = *(const float4*)(q + sb * CC + k0 + k4 * 4);
        }
        __syncthreads();

        const float* wb = W + (size_t)r * CC + k0;
#pragma unroll 4
        for (int k4 = 0; k4 < 64; k4++) {
            float4 qv = qs4[k4 * 32 + lane];
            float4 w0 = *(const float4*)(wb + k4 * 4);
            float4 w1 = *(const float4*)(wb + CC + k4 * 4);
            float4 w2 = *(const float4*)(wb + 2 * CC + k4 * 4);
            float4 w3 = *(const float4*)(wb + 3 * CC + k4 * 4);
            acc0 = fmaf(w0.x, qv.x, acc0); acc0 = fmaf(w0.y, qv.y, acc0);
            acc0 = fmaf(w0.z, qv.z, acc0); acc0 = fmaf(w0.w, qv.w, acc0);
            acc1 = fmaf(w1.x, qv.x, acc1); acc1 = fmaf(w1.y, qv.y, acc1);
            acc1 = fmaf(w1.z, qv.z, acc1); acc1 = fmaf(w1.w, qv.w, acc1);
            acc2 = fmaf(w2.x, qv.x, acc2); acc2 = fmaf(w2.y, qv.y, acc2);
            acc2 = fmaf(w2.z, qv.z, acc2); acc2 = fmaf(w2.w, qv.w, acc2);
            acc3 = fmaf(w3.x, qv.x, acc3); acc3 = fmaf(w3.y, qv.y, acc3);
            acc3 = fmaf(w3.z, qv.z, acc3); acc3 = fmaf(w3.w, qv.w, acc3);
        }
    }

    float accs[4] = {acc0, acc1, acc2, acc3};
#pragma unroll
    for (int j = 0; j < 4; j++) {
        int row = r + j;
        float v = accs[j] + Bi[row];
        if (is_sa) {
            g_saq[lane * CC + row] = v;
        } else {
            int c = row / KWW;
            int w = row - c * KWW;
            g_ker[(lane * KWW + w) * CC + c] = v;
        }
    }
}

// ============ kernel 2: fused flash pass ============
// grid = BB*NC blocks of 256. Block (b, chunk): 32 t-rows.
// Phase A: logits (outer loop over c-slices; side data in registers).
// Warp-0 softmax stats. Phase B: weighted v accumulation.
__global__ void __launch_bounds__(256) k_fused(
    const float* __restrict__ k1, const float* __restrict__ k2,
    const float* __restrict__ v1, const float* __restrict__ v2,
    const float* __restrict__ a1w, const float* __restrict__ k_mask) {
    __shared__ __align__(16) float s_sq[CC], s_aw[CC], s_r0[CC], s_r1[CC], s_r2[CC];
    __shared__ float sA1[TC], sS0[TC], sS1[TC], sS2[TC], sW1[TC], sW2[TC];
    __shared__ float sEdge[2];

    int bid = blockIdx.x;
    int b  = bid >> 5;           // / NC
    int c  = bid & (NC - 1);
    int t0 = c * TC;
    int tid = threadIdx.x;
    int warp = tid >> 5;
    int lane = tid & 31;

    {   // stage side data (CC/4 == 256 == blockDim)
        int i = tid;
        ((float4*)s_sq)[i] = ((const float4*)(g_saq + b * CC))[i];
        ((float4*)s_aw)[i] = ((const float4*)a1w)[i];
        ((float4*)s_r0)[i] = ((const float4*)(g_ker + (b * KWW + 0) * CC))[i];
        ((float4*)s_r1)[i] = ((const float4*)(g_ker + (b * KWW + 1) * CC))[i];
        ((float4*)s_r2)[i] = ((const float4*)(g_ker + (b * KWW + 2) * CC))[i];
    }
    __syncthreads();

    // ---- Phase A: warp handles 4 t-rows; outer loop over c-slices ----
    {
        int i0 = warp * 4;                       // rows i0..i0+3
        const float4* row0p1 = (const float4*)(k1 + (size_t)((t0 + i0) * BB + b) * CC);
        const float4* row0p2 = (const float4*)(k2 + (size_t)((t0 + i0) * BB + b) * CC);
        const int rstride = BB * (CC / 4);       // float4 stride between t-rows

        float aA[4] = {0.f, 0.f, 0.f, 0.f};
        float a0[4] = {0.f, 0.f, 0.f, 0.f};
        float a1_[4] = {0.f, 0.f, 0.f, 0.f};
        float a2_[4] = {0.f, 0.f, 0.f, 0.f};

#pragma unroll
        for (int q = 0; q < 8; q++) {
            int c4 = q * 32 + lane;
            float4 sv = ((const float4*)s_sq)[c4];
            float4 av = ((const float4*)s_aw)[c4];
            float4 r0 = ((const float4*)s_r0)[c4];
            float4 r1 = ((const float4*)s_r1)[c4];
            float4 r2 = ((const float4*)s_r2)[c4];

#pragma unroll
            for (int j = 0; j < 4; j++) {
                float4 x1 = row0p1[(size_t)j * rstride + c4];
                float4 x2 = row0p2[(size_t)j * rstride + c4];

                aA[j] = fmaf(tanh_approx(sv.x + x1.x), av.x, aA[j]);
                aA[j] = fmaf(tanh_approx(sv.y + x1.y), av.y, aA[j]);
                aA[j] = fmaf(tanh_approx(sv.z + x1.z), av.z, aA[j]);
                aA[j] = fmaf(tanh_approx(sv.w + x1.w), av.w, aA[j]);

                a0[j] = fmaf(r0.x, x2.x, a0[j]); a0[j] = fmaf(r0.y, x2.y, a0[j]);
                a0[j] = fmaf(r0.z, x2.z, a0[j]); a0[j] = fmaf(r0.w, x2.w, a0[j]);
                a1_[j] = fmaf(r1.x, x2.x, a1_[j]); a1_[j] = fmaf(r1.y, x2.y, a1_[j]);
                a1_[j] = fmaf(r1.z, x2.z, a1_[j]); a1_[j] = fmaf(r1.w, x2.w, a1_[j]);
                a2_[j] = fmaf(r2.x, x2.x, a2_[j]); a2_[j] = fmaf(r2.y, x2.y, a2_[j]);
                a2_[j] = fmaf(r2.z, x2.z, a2_[j]); a2_[j] = fmaf(r2.w, x2.w, a2_[j]);
            }
        }

#pragma unroll
        for (int j = 0; j < 4; j++) {
            float vA = aA[j], v0 = a0[j], v1r = a1_[j], v2r = a2_[j];
#pragma unroll
            for (int o = 16; o > 0; o >>= 1) {
                vA += __shfl_xor_sync(0xffffffffu, vA, o);
                v0 += __shfl_xor_sync(0xffffffffu, v0, o);
                v1r += __shfl_xor_sync(0xffffffffu, v1r, o);
                v2r += __shfl_xor_sync(0xffffffffu, v2r, o);
            }
            if (lane == 0) {
                int i = i0 + j;
                sA1[i] = vA; sS0[i] = v0; sS1[i] = v1r; sS2[i] = v2r;
            }
        }
    }

    // boundary tap dots
    if (warp == 0) {
        float s = 0.f;
        if (t0 > 0) {
            const float4* kp = (const float4*)(k2 + (size_t)((t0 - 1) * BB + b) * CC);
#pragma unroll
            for (int q = 0; q < 8; q++) {
                int c4 = q * 32 + lane;
                float4 x = kp[c4];
                float4 r = ((const float4*)s_r0)[c4];
                s += r.x * x.x + r.y * x.y + r.z * x.z + r.w * x.w;
            }
        }
#pragma unroll
        for (int o = 16; o > 0; o >>= 1) s += __shfl_xor_sync(0xffffffffu, s, o);
        if (lane == 0) sEdge[0] = s;
    } else if (warp == 1) {
        float s = 0.f;
        if (t0 + TC < TT) {
            const float4* kp = (const float4*)(k2 + (size_t)((t0 + TC) * BB + b) * CC);
#pragma unroll
            for (int q = 0; q < 8; q++) {
                int c4 = q * 32 + lane;
                float4 x = kp[c4];
                float4 r = ((const float4*)s_r2)[c4];
                s += r.x * x.x + r.y * x.y + r.z * x.z + r.w * x.w;
            }
        }
#pragma unroll
        for (int o = 16; o > 0; o >>= 1) s += __shfl_xor_sync(0xffffffffu, s, o);
        if (lane == 0) sEdge[1] = s;
    }
    __syncthreads();

    // ---- chunk softmax stats: single warp (TC == 32) ----
    if (warp == 0) {
        float a1v = sA1[lane];
        float a2v = sS1[lane]
                  + (lane > 0      ? sS0[lane - 1] : sEdge[0])
                  + (lane < TC - 1 ? sS2[lane + 1] : sEdge[1]);
        float mk = k_mask[(t0 + lane) * BB + b];

        float m1 = a1v, m2 = a2v;
#pragma unroll
        for (int o = 16; o > 0; o >>= 1) {
            m1 = fmaxf(m1, __shfl_xor_sync(0xffffffffu, m1, o));
            m2 = fmaxf(m2, __shfl_xor_sync(0xffffffffu, m2, o));
        }
        float w1 = expf(a1v - m1) * mk;
        float w2 = expf(a2v - m2) * mk;
        sW1[lane] = w1;
        sW2[lane] = w2;
        float ws1 = w1, ws2 = w2;
#pragma unroll
        for (int o = 16; o > 0; o >>= 1) {
            ws1 += __shfl_xor_sync(0xffffffffu, ws1, o);
            ws2 += __shfl_xor_sync(0xffffffffu, ws2, o);
        }
        if (lane == 0)
            *(float4*)(g_pm + bid * 4) = make_float4(m1, m2, ws1, ws2);
    }
    __syncthreads();

    // ---- Phase B: weighted v accumulation ----
    float4 A1 = make_float4(0.f, 0.f, 0.f, 0.f);
    float4 A2 = make_float4(0.f, 0.f, 0.f, 0.f);
#pragma unroll 4
    for (int i = 0; i < TC; i++) {
        int t = t0 + i;
        float4 xa = ((const float4*)v1)[(size_t)(t * BB + b) * (CC / 4) + tid];
        float4 xb = ((const float4*)v2)[(size_t)(t * BB + b) * (CC / 4) + tid];
        float u1 = sW1[i];
        float u2 = sW2[i];
        A1.x = fmaf(u1, xa.x, A1.x); A1.y = fmaf(u1, xa.y, A1.y);
        A1.z = fmaf(u1, xa.z, A1.z); A1.w = fmaf(u1, xa.w, A1.w);
        A2.x = fmaf(u2, xb.x, A2.x); A2.y = fmaf(u2, xb.y, A2.y);
        A2.z = fmaf(u2, xb.z, A2.z); A2.w = fmaf(u2, xb.w, A2.w);
    }
    ((float4*)g_pacc1)[(size_t)bid * (CC / 4) + tid] = A1;
    ((float4*)g_pacc2)[(size_t)bid * (CC / 4) + tid] = A2;
}

// ============ kernel 3: combine chunks + LayerNorm ============
__device__ __forceinline__ float bred1(float v, float* sm) {
    int lane = threadIdx.x & 31;
    int warp = threadIdx.x >> 5;
#pragma unroll
    for (int o = 16; o > 0; o >>= 1) v += __shfl_xor_sync(0xffffffffu, v, o);
    if (lane == 0) sm[warp] = v;
    __syncthreads();
    float a = sm[lane & 7];
#pragma unroll
    for (int o = 4; o > 0; o >>= 1) a += __shfl_xor_sync(0xffffffffu, a, o);
    a = __shfl_sync(0xffffffffu, a, 0);
    __syncthreads();
    return a;
}

__global__ void __launch_bounds__(256) k_combine(
    const float* __restrict__ ln_g, const float* __restrict__ ln_b,
    float* __restrict__ out) {
    __shared__ float sf1[NC], sf2[NC], sS[2], sm[8];
    int b = blockIdx.x;
    int tid = threadIdx.x;

    if (tid < NC) {     // NC == 32: one warp
        float4 pm = *(const float4*)(g_pm + (b * NC + tid) * 4);
        float M1 = pm.x, M2 = pm.y;
#pragma unroll
        for (int o = 16; o > 0; o >>= 1) {
            M1 = fmaxf(M1, __shfl_xor_sync(0xffffffffu, M1, o));
            M2 = fmaxf(M2, __shfl_xor_sync(0xffffffffu, M2, o));
        }
        float f1 = expf(pm.x - M1);
        float f2 = expf(pm.y - M2);
        sf1[tid] = f1;
        sf2[tid] = f2;
        float t1 = pm.z * f1, t2 = pm.w * f2;
#pragma unroll
        for (int o = 16; o > 0; o >>= 1) {
            t1 += __shfl_xor_sync(0xffffffffu, t1, o);
            t2 += __shfl_xor_sync(0xffffffffu, t2, o);
        }
        if (tid == 0) { sS[0] = t1; sS[1] = t2; }
    }
    __syncthreads();

    float i1 = 1.f / sS[0];
    float i2 = 1.f / sS[1];

    float4 x = make_float4(0.f, 0.f, 0.f, 0.f);
#pragma unroll 4
    for (int c = 0; c < NC; c++) {
        float g1 = sf1[c] * i1;
        float g2 = sf2[c] * i2;
        float4 p1 = ((const float4*)g_pacc1)[(size_t)(b * NC + c) * (CC / 4) + tid];
        float4 p2 = ((const float4*)g_pacc2)[(size_t)(b * NC + c) * (CC / 4) + tid];
        x.x += g1 * p1.x + g2 * p2.x;
        x.y += g1 * p1.y + g2 * p2.y;
        x.z += g1 * p1.z + g2 * p2.z;
        x.w += g1 * p1.w + g2 * p2.w;
    }

    float s = x.x + x.y + x.z + x.w;
    float total = bred1(s, sm);
    float mu = total * (1.f / (float)CC);

    float dx0 = x.x - mu, dx1 = x.y - mu, dx2 = x.z - mu, dx3 = x.w - mu;
    float sq = dx0 * dx0 + dx1 * dx1 + dx2 * dx2 + dx3 * dx3;
    float tot2 = bred1(sq, sm);
    float inv = rsqrtf(tot2 * (1.f / (float)CC) + 1e-6f);

    int d = tid * 4;
    float4 g = *(const float4*)(ln_g + d);
    float4 bb = *(const float4*)(ln_b + d);
    float4 o;
    o.x = dx0 * inv * g.x + bb.x;
    o.y = dx1 * inv * g.y + bb.y;
    o.z = dx2 * inv * g.z + bb.z;
    o.w = dx3 * inv * g.w + bb.w;
    *(float4*)(out + b * CC + d) = o;
}

// ---------------- launch ----------------
extern "C" void kernel_launch(void* const* d_in, const int* in_sizes, int n_in,
                              void* d_out, int out_size) {
    const float* q1     = (const float*)d_in[0];
    const float* k1     = (const float*)d_in[1];
    const float* v1     = (const float*)d_in[2];
    const float* q2     = (const float*)d_in[3];
    const float* k2     = (const float*)d_in[4];
    const float* v2     = (const float*)d_in[5];
    const float* k_mask = (const float*)d_in[6];
    const float* sa_w   = (const float*)d_in[7];
    const float* sa_b   = (const float*)d_in[8];
    const float* a1_w   = (const float*)d_in[9];
    // d_in[10] = a1_b : constant shift, cancels in softmax — unused
    const float* qk_w   = (const float*)d_in[11];
    const float* qk_b   = (const float*)d_in[12];
    const float* ln_g   = (const float*)d_in[13];
    const float* ln_b   = (const float*)d_in[14];
    float* out = (float*)d_out;

    k_rowgemm<<<128, 256>>>(q1, q2, sa_w, sa_b, qk_w, qk_b);
    k_fused<<<BB * NC, 256>>>(k1, k2, v1, v2, a1_w, k_mask);
    k_combine<<<BB, 256>>>(ln_g, ln_b, out);
}

// round 7
// speedup vs baseline: 1.8192x; 1.2988x over previous
#include <cuda_runtime.h>
#include <math.h>

#define TT   1024
#define BB   32
#define CC   1024
#define KWW  3
#define NC   16      // t-chunks in fused pass
#define TC   64      // t per chunk (NC*TC == TT)
#define KS   4       // k-splits in rowgemm
#define KSL  256     // k per split

// ---------------- scratch ----------------
__device__ __align__(16) float g_wp[KS][4096 * BB];     // rowgemm partials [ks][row*32+b]
__device__ __align__(16) float g_saq[BB * CC];          // sa(q1) [b][c]
__device__ __align__(16) float g_ker[BB * KWW * CC];    // kernels [b][w][c]
__device__ __align__(16) float g_pm[BB * NC * 4];       // per chunk: m1,m2,ws1,ws2
__device__ __align__(16) float g_pacc1[BB * NC * CC];   // chunk partial acc path1
__device__ __align__(16) float g_pacc2[BB * NC * CC];   // chunk partial acc path2

__device__ __forceinline__ float tanh_approx(float x) {
    float y;
    asm("tanh.approx.f32 %0, %1;" : "=f"(y) : "f"(x));
    return y;
}

// ============ kernel 1: row GEMMs, coalesced-W ============
// grid 1024 = 256 row-blocks (16 rows) x KS k-splits. Block 256 thr, warp = 2 rows.
// Lane owns consecutive float4 of W (coalesced LDG.128). q k-slice staged in smem
// [b][k] (conflict-free LDS.128). Butterfly reduce; partials to g_wp[ks].
__global__ void __launch_bounds__(256) k_rowgemm(
    const float* __restrict__ q1, const float* __restrict__ q2,
    const float* __restrict__ sa_w, const float* __restrict__ qk_w) {
    __shared__ __align__(16) float4 qs4[BB * (KSL / 4)];   // [b][k4], 32 KB

    int tid  = threadIdx.x;
    int warp = tid >> 5;
    int lane = tid & 31;

    int ks = blockIdx.x & (KS - 1);
    int rb = blockIdx.x >> 2;              // 0..255
    bool is_sa = rb < 64;
    int r0 = rb * 16 + warp * 2;           // global row (0..4095)
    int rw = is_sa ? r0 : r0 - 1024;

    const float* q = is_sa ? q1 : q2;
    const float* W = is_sa ? sa_w : qk_w;

    {   // stage q[b][ks*KSL .. +KSL)
        int k04 = ks * (KSL / 4);
#pragma unroll
        for (int i = 0; i < 8; i++) {
            int idx = i * 256 + tid;       // 0..2047
            int b   = idx >> 6;
            int kl4 = idx & 63;
            qs4[idx] = ((const float4*)q)[b * (CC / 4) + k04 + kl4];
        }
    }
    __syncthreads();

    float acc0[32], acc1[32];
#pragma unroll
    for (int b = 0; b < 32; b++) { acc0[b] = 0.f; acc1[b] = 0.f; }

    const float4* w0p = (const float4*)(W + (size_t)rw * CC);
    const float4* w1p = (const float4*)(W + (size_t)(rw + 1) * CC);
    int k04 = ks * (KSL / 4);

#pragma unroll
    for (int j = 0; j < 2; j++) {
        float4 w0 = w0p[k04 + j * 32 + lane];
        float4 w1 = w1p[k04 + j * 32 + lane];
#pragma unroll
        for (int b = 0; b < 32; b++) {
            float4 qv = qs4[b * 64 + j * 32 + lane];
            acc0[b] = fmaf(w0.x, qv.x, acc0[b]);
            acc0[b] = fmaf(w0.y, qv.y, acc0[b]);
            acc0[b] = fmaf(w0.z, qv.z, acc0[b]);
            acc0[b] = fmaf(w0.w, qv.w, acc0[b]);
            acc1[b] = fmaf(w1.x, qv.x, acc1[b]);
            acc1[b] = fmaf(w1.y, qv.y, acc1[b]);
            acc1[b] = fmaf(w1.z, qv.z, acc1[b]);
            acc1[b] = fmaf(w1.w, qv.w, acc1[b]);
        }
    }

#pragma unroll
    for (int b = 0; b < 32; b++) {
#pragma unroll
        for (int o = 16; o > 0; o >>= 1) {
            acc0[b] += __shfl_xor_sync(0xffffffffu, acc0[b], o);
            acc1[b] += __shfl_xor_sync(0xffffffffu, acc1[b], o);
        }
    }
#pragma unroll
    for (int b = 0; b < 32; b++) {
        if (lane == b) {
            g_wp[ks][r0 * 32 + b]       = acc0[b];
            g_wp[ks][(r0 + 1) * 32 + b] = acc1[b];
        }
    }
}

// ============ kernel 1b: sum k-splits + bias, scatter ============
__global__ void __launch_bounds__(256) k_wcombine(
    const float* __restrict__ sa_b, const float* __restrict__ qk_b) {
    int idx = blockIdx.x * 256 + threadIdx.x;   // 0 .. 4096*32-1
    int row = idx >> 5;
    int b   = idx & 31;
    float v = g_wp[0][idx] + g_wp[1][idx] + g_wp[2][idx] + g_wp[3][idx];
    if (row < 1024) {
        g_saq[b * CC + row] = v + sa_b[row];
    } else {
        int r = row - 1024;
        int c = r / KWW;
        int w = r - c * KWW;
        g_ker[(b * KWW + w) * CC + c] = v + qk_b[r];
    }
}

// ---------------- dual block reduction ----------------
__device__ __forceinline__ void bred2(float& v1, float& v2, float* sm, int sum_mode) {
    int lane = threadIdx.x & 31;
    int warp = threadIdx.x >> 5;
#pragma unroll
    for (int o = 16; o > 0; o >>= 1) {
        float o1 = __shfl_xor_sync(0xffffffffu, v1, o);
        float o2 = __shfl_xor_sync(0xffffffffu, v2, o);
        if (sum_mode) { v1 += o1; v2 += o2; }
        else          { v1 = fmaxf(v1, o1); v2 = fmaxf(v2, o2); }
    }
    if (lane == 0) { sm[warp] = v1; sm[8 + warp] = v2; }
    __syncthreads();
    float a = sm[lane & 7], b = sm[8 + (lane & 7)];
#pragma unroll
    for (int o = 4; o > 0; o >>= 1) {
        float oa = __shfl_xor_sync(0xffffffffu, a, o);
        float ob = __shfl_xor_sync(0xffffffffu, b, o);
        if (sum_mode) { a += oa; b += ob; }
        else          { a = fmaxf(a, oa); b = fmaxf(b, ob); }
    }
    v1 = __shfl_sync(0xffffffffu, a, 0);
    v2 = __shfl_sync(0xffffffffu, b, 0);
    __syncthreads();
}

// ============ kernel 2: fused flash pass (TC=64, NC=16) ============
__global__ void __launch_bounds__(256) k_fused(
    const float* __restrict__ k1, const float* __restrict__ k2,
    const float* __restrict__ v1, const float* __restrict__ v2,
    const float* __restrict__ a1w, const float* __restrict__ k_mask) {
    __shared__ __align__(16) float s_sq[CC], s_aw[CC], s_r0[CC], s_r1[CC], s_r2[CC];
    __shared__ float sA1[TC], sS0[TC], sS1[TC], sS2[TC], sW1[TC], sW2[TC];
    __shared__ float sEdge[2];
    __shared__ float sm[16];

    int bid = blockIdx.x;
    int b  = bid >> 4;
    int c  = bid & (NC - 1);
    int t0 = c * TC;
    int tid = threadIdx.x;
    int warp = tid >> 5;
    int lane = tid & 31;

    {
        int i = tid;
        ((float4*)s_sq)[i] = ((const float4*)(g_saq + b * CC))[i];
        ((float4*)s_aw)[i] = ((const float4*)a1w)[i];
        ((float4*)s_r0)[i] = ((const float4*)(g_ker + (b * KWW + 0) * CC))[i];
        ((float4*)s_r1)[i] = ((const float4*)(g_ker + (b * KWW + 1) * CC))[i];
        ((float4*)s_r2)[i] = ((const float4*)(g_ker + (b * KWW + 2) * CC))[i];
    }
    __syncthreads();

#pragma unroll
    for (int it = 0; it < TC / 8; ++it) {
        int i = it * 8 + warp;
        int t = t0 + i;
        const float4* k1p = (const float4*)(k1 + (size_t)(t * BB + b) * CC);
        const float4* k2p = (const float4*)(k2 + (size_t)(t * BB + b) * CC);

        float a1 = 0.f, s0 = 0.f, s1 = 0.f, s2 = 0.f;
#pragma unroll
        for (int q = 0; q < 8; q++) {
            int c4 = q * 32 + lane;
            float4 x1 = k1p[c4];
            float4 x2 = k2p[c4];
            float4 sv = ((const float4*)s_sq)[c4];
            float4 av = ((const float4*)s_aw)[c4];
            float4 r0 = ((const float4*)s_r0)[c4];
            float4 r1 = ((const float4*)s_r1)[c4];
            float4 r2 = ((const float4*)s_r2)[c4];

            a1 = fmaf(tanh_approx(sv.x + x1.x), av.x, a1);
            a1 = fmaf(tanh_approx(sv.y + x1.y), av.y, a1);
            a1 = fmaf(tanh_approx(sv.z + x1.z), av.z, a1);
            a1 = fmaf(tanh_approx(sv.w + x1.w), av.w, a1);

            s0 = fmaf(r0.x, x2.x, s0); s0 = fmaf(r0.y, x2.y, s0);
            s0 = fmaf(r0.z, x2.z, s0); s0 = fmaf(r0.w, x2.w, s0);
            s1 = fmaf(r1.x, x2.x, s1); s1 = fmaf(r1.y, x2.y, s1);
            s1 = fmaf(r1.z, x2.z, s1); s1 = fmaf(r1.w, x2.w, s1);
            s2 = fmaf(r2.x, x2.x, s2); s2 = fmaf(r2.y, x2.y, s2);
            s2 = fmaf(r2.z, x2.z, s2); s2 = fmaf(r2.w, x2.w, s2);
        }
#pragma unroll
        for (int o = 16; o > 0; o >>= 1) {
            a1 += __shfl_xor_sync(0xffffffffu, a1, o);
            s0 += __shfl_xor_sync(0xffffffffu, s0, o);
            s1 += __shfl_xor_sync(0xffffffffu, s1, o);
            s2 += __shfl_xor_sync(0xffffffffu, s2, o);
        }
        if (lane == 0) { sA1[i] = a1; sS0[i] = s0; sS1[i] = s1; sS2[i] = s2; }
    }

    if (warp == 0) {
        float s = 0.f;
        if (t0 > 0) {
            const float4* kp = (const float4*)(k2 + (size_t)((t0 - 1) * BB + b) * CC);
#pragma unroll
            for (int q = 0; q < 8; q++) {
                int c4 = q * 32 + lane;
                float4 x = kp[c4];
                float4 r = ((const float4*)s_r0)[c4];
                s += r.x * x.x + r.y * x.y + r.z * x.z + r.w * x.w;
            }
        }
#pragma unroll
        for (int o = 16; o > 0; o >>= 1) s += __shfl_xor_sync(0xffffffffu, s, o);
        if (lane == 0) sEdge[0] = s;
    } else if (warp == 1) {
        float s = 0.f;
        if (t0 + TC < TT) {
            const float4* kp = (const float4*)(k2 + (size_t)((t0 + TC) * BB + b) * CC);
#pragma unroll
            for (int q = 0; q < 8; q++) {
                int c4 = q * 32 + lane;
                float4 x = kp[c4];
                float4 r = ((const float4*)s_r2)[c4];
                s += r.x * x.x + r.y * x.y + r.z * x.z + r.w * x.w;
            }
        }
#pragma unroll
        for (int o = 16; o > 0; o >>= 1) s += __shfl_xor_sync(0xffffffffu, s, o);
        if (lane == 0) sEdge[1] = s;
    }
    __syncthreads();

    float a1v = -3.0e38f, a2v = -3.0e38f, mk = 0.f;
    if (tid < TC) {
        int i = tid;
        a1v = sA1[i];
        a2v = sS1[i]
            + (i > 0      ? sS0[i - 1] : sEdge[0])
            + (i < TC - 1 ? sS2[i + 1] : sEdge[1]);
        mk = k_mask[(t0 + i) * BB + b];
    }
    float m1 = a1v, m2 = a2v;
    bred2(m1, m2, sm, 0);

    float w1 = 0.f, w2 = 0.f;
    if (tid < TC) {
        w1 = expf(a1v - m1) * mk;
        w2 = expf(a2v - m2) * mk;
        sW1[tid] = w1;
        sW2[tid] = w2;
    }
    float ws1 = w1, ws2 = w2;
    bred2(ws1, ws2, sm, 1);

    if (tid == 0)
        *(float4*)(g_pm + bid * 4) = make_float4(m1, m2, ws1, ws2);
    __syncthreads();

    float4 A1 = make_float4(0.f, 0.f, 0.f, 0.f);
    float4 A2 = make_float4(0.f, 0.f, 0.f, 0.f);
#pragma unroll 4
    for (int i = 0; i < TC; i++) {
        int t = t0 + i;
        float4 xa = ((const float4*)v1)[(size_t)(t * BB + b) * (CC / 4) + tid];
        float4 xb = ((const float4*)v2)[(size_t)(t * BB + b) * (CC / 4) + tid];
        float u1 = sW1[i];
        float u2 = sW2[i];
        A1.x = fmaf(u1, xa.x, A1.x); A1.y = fmaf(u1, xa.y, A1.y);
        A1.z = fmaf(u1, xa.z, A1.z); A1.w = fmaf(u1, xa.w, A1.w);
        A2.x = fmaf(u2, xb.x, A2.x); A2.y = fmaf(u2, xb.y, A2.y);
        A2.z = fmaf(u2, xb.z, A2.z); A2.w = fmaf(u2, xb.w, A2.w);
    }
    ((float4*)g_pacc1)[(size_t)bid * (CC / 4) + tid] = A1;
    ((float4*)g_pacc2)[(size_t)bid * (CC / 4) + tid] = A2;
}

// ============ kernel 3: combine chunks + LayerNorm ============
__device__ __forceinline__ float bred1(float v, float* sm) {
    int lane = threadIdx.x & 31;
    int warp = threadIdx.x >> 5;
#pragma unroll
    for (int o = 16; o > 0; o >>= 1) v += __shfl_xor_sync(0xffffffffu, v, o);
    if (lane == 0) sm[warp] = v;
    __syncthreads();
    float a = sm[lane & 7];
#pragma unroll
    for (int o = 4; o > 0; o >>= 1) a += __shfl_xor_sync(0xffffffffu, a, o);
    a = __shfl_sync(0xffffffffu, a, 0);
    __syncthreads();
    return a;
}

__global__ void __launch_bounds__(256) k_combine(
    const float* __restrict__ ln_g, const float* __restrict__ ln_b,
    float* __restrict__ out) {
    __shared__ float sm[8];
    int b = blockIdx.x;
    int tid = threadIdx.x;

    float m1c[NC], m2c[NC], s1c[NC], s2c[NC];
    float M1 = -3.0e38f, M2 = -3.0e38f;
#pragma unroll
    for (int c = 0; c < NC; c++) {
        float4 pm = *(const float4*)(g_pm + (b * NC + c) * 4);
        m1c[c] = pm.x; m2c[c] = pm.y; s1c[c] = pm.z; s2c[c] = pm.w;
        M1 = fmaxf(M1, pm.x);
        M2 = fmaxf(M2, pm.y);
    }
    float S1 = 0.f, S2 = 0.f;
    float f1[NC], f2[NC];
#pragma unroll
    for (int c = 0; c < NC; c++) {
        f1[c] = expf(m1c[c] - M1);
        f2[c] = expf(m2c[c] - M2);
        S1 += s1c[c] * f1[c];
        S2 += s2c[c] * f2[c];
    }
    float i1 = 1.f / S1, i2 = 1.f / S2;

    float4 x = make_float4(0.f, 0.f, 0.f, 0.f);
#pragma unroll
    for (int c = 0; c < NC; c++) {
        float g1 = f1[c] * i1;
        float g2 = f2[c] * i2;
        float4 p1 = ((const float4*)g_pacc1)[(size_t)(b * NC + c) * (CC / 4) + tid];
        float4 p2 = ((const float4*)g_pacc2)[(size_t)(b * NC + c) * (CC / 4) + tid];
        x.x += g1 * p1.x + g2 * p2.x;
        x.y += g1 * p1.y + g2 * p2.y;
        x.z += g1 * p1.z + g2 * p2.z;
        x.w += g1 * p1.w + g2 * p2.w;
    }

    float s = x.x + x.y + x.z + x.w;
    float total = bred1(s, sm);
    float mu = total * (1.f / (float)CC);

    float dx0 = x.x - mu, dx1 = x.y - mu, dx2 = x.z - mu, dx3 = x.w - mu;
    float sq = dx0 * dx0 + dx1 * dx1 + dx2 * dx2 + dx3 * dx3;
    float tot2 = bred1(sq, sm);
    float inv = rsqrtf(tot2 * (1.f / (float)CC) + 1e-6f);

    int d = tid * 4;
    float4 g = *(const float4*)(ln_g + d);
    float4 bb = *(const float4*)(ln_b + d);
    float4 o;
    o.x = dx0 * inv * g.x + bb.x;
    o.y = dx1 * inv * g.y + bb.y;
    o.z = dx2 * inv * g.z + bb.z;
    o.w = dx3 * inv * g.w + bb.w;
    *(float4*)(out + b * CC + d) = o;
}

// ---------------- launch ----------------
extern "C" void kernel_launch(void* const* d_in, const int* in_sizes, int n_in,
                              void* d_out, int out_size) {
    const float* q1     = (const float*)d_in[0];
    const float* k1     = (const float*)d_in[1];
    const float* v1     = (const float*)d_in[2];
    const float* q2     = (const float*)d_in[3];
    const float* k2     = (const float*)d_in[4];
    const float* v2     = (const float*)d_in[5];
    const float* k_mask = (const float*)d_in[6];
    const float* sa_w   = (const float*)d_in[7];
    const float* sa_b   = (const float*)d_in[8];
    const float* a1_w   = (const float*)d_in[9];
    // d_in[10] = a1_b : constant shift, cancels in softmax — unused
    const float* qk_w   = (const float*)d_in[11];
    const float* qk_b   = (const float*)d_in[12];
    const float* ln_g   = (const float*)d_in[13];
    const float* ln_b   = (const float*)d_in[14];
    float* out = (float*)d_out;

    k_rowgemm<<<1024, 256>>>(q1, q2, sa_w, qk_w);
    k_wcombine<<<512, 256>>>(sa_b, qk_b);
    k_fused<<<BB * NC, 256>>>(k1, k2, v1, v2, a1_w, k_mask);
    k_combine<<<BB, 256>>>(ln_g, ln_b, out);
}

// round 8
// speedup vs baseline: 2.1826x; 1.1997x over previous
#include <cuda_runtime.h>
#include <math.h>

#define TT   1024
#define BB   32
#define CC   1024
#define KWW  3
#define NC   16      // t-chunks in fused pass
#define TC   64      // t per chunk (NC*TC == TT)
#define KS   4       // k-splits in rowgemm
#define KSL  256     // k per split
#define NSL  8       // feature slices in combine stage 1
#define SLW  128     // features per slice (NSL*SLW == CC)

// ---------------- scratch ----------------
__device__ __align__(16) float g_wp[KS][4096 * BB];     // rowgemm partials
__device__ __align__(16) float g_saq[BB * CC];          // sa(q1) [b][c]
__device__ __align__(16) float g_ker[BB * KWW * CC];    // kernels [b][w][c]
__device__ __align__(16) float g_pm[BB * NC * 4];       // per chunk: m1,m2,ws1,ws2
__device__ __align__(16) float g_pacc1[BB * NC * CC];   // chunk partial acc path1
__device__ __align__(16) float g_pacc2[BB * NC * CC];   // chunk partial acc path2
__device__ __align__(16) float g_x[BB * CC];            // combined attend (pre-LN)
__device__ __align__(16) float g_lnp[BB * NSL * 2];     // LN partials (sum, sumsq)

__device__ __forceinline__ float tanh_approx(float x) {
    float y;
    asm("tanh.approx.f32 %0, %1;" : "=f"(y) : "f"(x));
    return y;
}

// ============ kernel 1: row GEMMs, coalesced-W ============
__global__ void __launch_bounds__(256) k_rowgemm(
    const float* __restrict__ q1, const float* __restrict__ q2,
    const float* __restrict__ sa_w, const float* __restrict__ qk_w) {
    __shared__ __align__(16) float4 qs4[BB * (KSL / 4)];   // [b][k4], 32 KB

    int tid  = threadIdx.x;
    int warp = tid >> 5;
    int lane = tid & 31;

    int ks = blockIdx.x & (KS - 1);
    int rb = blockIdx.x >> 2;              // 0..255
    bool is_sa = rb < 64;
    int r0 = rb * 16 + warp * 2;           // global row (0..4095)
    int rw = is_sa ? r0 : r0 - 1024;

    const float* q = is_sa ? q1 : q2;
    const float* W = is_sa ? sa_w : qk_w;

    {
        int k04 = ks * (KSL / 4);
#pragma unroll
        for (int i = 0; i < 8; i++) {
            int idx = i * 256 + tid;
            int b   = idx >> 6;
            int kl4 = idx & 63;
            qs4[idx] = ((const float4*)q)[b * (CC / 4) + k04 + kl4];
        }
    }
    __syncthreads();

    float acc0[32], acc1[32];
#pragma unroll
    for (int b = 0; b < 32; b++) { acc0[b] = 0.f; acc1[b] = 0.f; }

    const float4* w0p = (const float4*)(W + (size_t)rw * CC);
    const float4* w1p = (const float4*)(W + (size_t)(rw + 1) * CC);
    int k04 = ks * (KSL / 4);

#pragma unroll
    for (int j = 0; j < 2; j++) {
        float4 w0 = w0p[k04 + j * 32 + lane];
        float4 w1 = w1p[k04 + j * 32 + lane];
#pragma unroll
        for (int b = 0; b < 32; b++) {
            float4 qv = qs4[b * 64 + j * 32 + lane];
            acc0[b] = fmaf(w0.x, qv.x, acc0[b]);
            acc0[b] = fmaf(w0.y, qv.y, acc0[b]);
            acc0[b] = fmaf(w0.z, qv.z, acc0[b]);
            acc0[b] = fmaf(w0.w, qv.w, acc0[b]);
            acc1[b] = fmaf(w1.x, qv.x, acc1[b]);
            acc1[b] = fmaf(w1.y, qv.y, acc1[b]);
            acc1[b] = fmaf(w1.z, qv.z, acc1[b]);
            acc1[b] = fmaf(w1.w, qv.w, acc1[b]);
        }
    }

#pragma unroll
    for (int b = 0; b < 32; b++) {
#pragma unroll
        for (int o = 16; o > 0; o >>= 1) {
            acc0[b] += __shfl_xor_sync(0xffffffffu, acc0[b], o);
            acc1[b] += __shfl_xor_sync(0xffffffffu, acc1[b], o);
        }
    }
#pragma unroll
    for (int b = 0; b < 32; b++) {
        if (lane == b) {
            g_wp[ks][r0 * 32 + b]       = acc0[b];
            g_wp[ks][(r0 + 1) * 32 + b] = acc1[b];
        }
    }
}

// ============ kernel 1b: sum k-splits + bias, scatter ============
__global__ void __launch_bounds__(256) k_wcombine(
    const float* __restrict__ sa_b, const float* __restrict__ qk_b) {
    int idx = blockIdx.x * 256 + threadIdx.x;
    int row = idx >> 5;
    int b   = idx & 31;
    float v = g_wp[0][idx] + g_wp[1][idx] + g_wp[2][idx] + g_wp[3][idx];
    if (row < 1024) {
        g_saq[b * CC + row] = v + sa_b[row];
    } else {
        int r = row - 1024;
        int c = r / KWW;
        int w = r - c * KWW;
        g_ker[(b * KWW + w) * CC + c] = v + qk_b[r];
    }
}

// ---------------- dual block reduction ----------------
__device__ __forceinline__ void bred2(float& v1, float& v2, float* sm, int sum_mode) {
    int lane = threadIdx.x & 31;
    int warp = threadIdx.x >> 5;
#pragma unroll
    for (int o = 16; o > 0; o >>= 1) {
        float o1 = __shfl_xor_sync(0xffffffffu, v1, o);
        float o2 = __shfl_xor_sync(0xffffffffu, v2, o);
        if (sum_mode) { v1 += o1; v2 += o2; }
        else          { v1 = fmaxf(v1, o1); v2 = fmaxf(v2, o2); }
    }
    if (lane == 0) { sm[warp] = v1; sm[8 + warp] = v2; }
    __syncthreads();
    float a = sm[lane & 7], b = sm[8 + (lane & 7)];
#pragma unroll
    for (int o = 4; o > 0; o >>= 1) {
        float oa = __shfl_xor_sync(0xffffffffu, a, o);
        float ob = __shfl_xor_sync(0xffffffffu, b, o);
        if (sum_mode) { a += oa; b += ob; }
        else          { a = fmaxf(a, oa); b = fmaxf(b, ob); }
    }
    v1 = __shfl_sync(0xffffffffu, a, 0);
    v2 = __shfl_sync(0xffffffffu, b, 0);
    __syncthreads();
}

// ============ kernel 2: fused flash pass (TC=64, NC=16) ============
__global__ void __launch_bounds__(256) k_fused(
    const float* __restrict__ k1, const float* __restrict__ k2,
    const float* __restrict__ v1, const float* __restrict__ v2,
    const float* __restrict__ a1w, const float* __restrict__ k_mask) {
    __shared__ __align__(16) float s_sq[CC], s_aw[CC], s_r0[CC], s_r1[CC], s_r2[CC];
    __shared__ float sA1[TC], sS0[TC], sS1[TC], sS2[TC], sW1[TC], sW2[TC];
    __shared__ float sEdge[2];
    __shared__ float sm[16];

    int bid = blockIdx.x;
    int b  = bid >> 4;
    int c  = bid & (NC - 1);
    int t0 = c * TC;
    int tid = threadIdx.x;
    int warp = tid >> 5;
    int lane = tid & 31;

    {
        int i = tid;
        ((float4*)s_sq)[i] = ((const float4*)(g_saq + b * CC))[i];
        ((float4*)s_aw)[i] = ((const float4*)a1w)[i];
        ((float4*)s_r0)[i] = ((const float4*)(g_ker + (b * KWW + 0) * CC))[i];
        ((float4*)s_r1)[i] = ((const float4*)(g_ker + (b * KWW + 1) * CC))[i];
        ((float4*)s_r2)[i] = ((const float4*)(g_ker + (b * KWW + 2) * CC))[i];
    }
    __syncthreads();

#pragma unroll
    for (int it = 0; it < TC / 8; ++it) {
        int i = it * 8 + warp;
        int t = t0 + i;
        const float4* k1p = (const float4*)(k1 + (size_t)(t * BB + b) * CC);
        const float4* k2p = (const float4*)(k2 + (size_t)(t * BB + b) * CC);

        float a1 = 0.f, s0 = 0.f, s1 = 0.f, s2 = 0.f;
#pragma unroll
        for (int q = 0; q < 8; q++) {
            int c4 = q * 32 + lane;
            float4 x1 = __ldcs(k1p + c4);      // streaming: read-once data
            float4 x2 = __ldcs(k2p + c4);
            float4 sv = ((const float4*)s_sq)[c4];
            float4 av = ((const float4*)s_aw)[c4];
            float4 r0 = ((const float4*)s_r0)[c4];
            float4 r1 = ((const float4*)s_r1)[c4];
            float4 r2 = ((const float4*)s_r2)[c4];

            a1 = fmaf(tanh_approx(sv.x + x1.x), av.x, a1);
            a1 = fmaf(tanh_approx(sv.y + x1.y), av.y, a1);
            a1 = fmaf(tanh_approx(sv.z + x1.z), av.z, a1);
            a1 = fmaf(tanh_approx(sv.w + x1.w), av.w, a1);

            s0 = fmaf(r0.x, x2.x, s0); s0 = fmaf(r0.y, x2.y, s0);
            s0 = fmaf(r0.z, x2.z, s0); s0 = fmaf(r0.w, x2.w, s0);
            s1 = fmaf(r1.x, x2.x, s1); s1 = fmaf(r1.y, x2.y, s1);
            s1 = fmaf(r1.z, x2.z, s1); s1 = fmaf(r1.w, x2.w, s1);
            s2 = fmaf(r2.x, x2.x, s2); s2 = fmaf(r2.y, x2.y, s2);
            s2 = fmaf(r2.z, x2.z, s2); s2 = fmaf(r2.w, x2.w, s2);
        }
#pragma unroll
        for (int o = 16; o > 0; o >>= 1) {
            a1 += __shfl_xor_sync(0xffffffffu, a1, o);
            s0 += __shfl_xor_sync(0xffffffffu, s0, o);
            s1 += __shfl_xor_sync(0xffffffffu, s1, o);
            s2 += __shfl_xor_sync(0xffffffffu, s2, o);
        }
        if (lane == 0) { sA1[i] = a1; sS0[i] = s0; sS1[i] = s1; sS2[i] = s2; }
    }

    if (warp == 0) {
        float s = 0.f;
        if (t0 > 0) {
            const float4* kp = (const float4*)(k2 + (size_t)((t0 - 1) * BB + b) * CC);
#pragma unroll
            for (int q = 0; q < 8; q++) {
                int c4 = q * 32 + lane;
                float4 x = kp[c4];
                float4 r = ((const float4*)s_r0)[c4];
                s += r.x * x.x + r.y * x.y + r.z * x.z + r.w * x.w;
            }
        }
#pragma unroll
        for (int o = 16; o > 0; o >>= 1) s += __shfl_xor_sync(0xffffffffu, s, o);
        if (lane == 0) sEdge[0] = s;
    } else if (warp == 1) {
        float s = 0.f;
        if (t0 + TC < TT) {
            const float4* kp = (const float4*)(k2 + (size_t)((t0 + TC) * BB + b) * CC);
#pragma unroll
            for (int q = 0; q < 8; q++) {
                int c4 = q * 32 + lane;
                float4 x = kp[c4];
                float4 r = ((const float4*)s_r2)[c4];
                s += r.x * x.x + r.y * x.y + r.z * x.z + r.w * x.w;
            }
        }
#pragma unroll
        for (int o = 16; o > 0; o >>= 1) s += __shfl_xor_sync(0xffffffffu, s, o);
        if (lane == 0) sEdge[1] = s;
    }
    __syncthreads();

    float a1v = -3.0e38f, a2v = -3.0e38f, mk = 0.f;
    if (tid < TC) {
        int i = tid;
        a1v = sA1[i];
        a2v = sS1[i]
            + (i > 0      ? sS0[i - 1] : sEdge[0])
            + (i < TC - 1 ? sS2[i + 1] : sEdge[1]);
        mk = k_mask[(t0 + i) * BB + b];
    }
    float m1 = a1v, m2 = a2v;
    bred2(m1, m2, sm, 0);

    float w1 = 0.f, w2 = 0.f;
    if (tid < TC) {
        w1 = expf(a1v - m1) * mk;
        w2 = expf(a2v - m2) * mk;
        sW1[tid] = w1;
        sW2[tid] = w2;
    }
    float ws1 = w1, ws2 = w2;
    bred2(ws1, ws2, sm, 1);

    if (tid == 0)
        *(float4*)(g_pm + bid * 4) = make_float4(m1, m2, ws1, ws2);
    __syncthreads();

    float4 A1 = make_float4(0.f, 0.f, 0.f, 0.f);
    float4 A2 = make_float4(0.f, 0.f, 0.f, 0.f);
#pragma unroll 4
    for (int i = 0; i < TC; i++) {
        int t = t0 + i;
        float4 xa = __ldcs(((const float4*)v1) + (size_t)(t * BB + b) * (CC / 4) + tid);
        float4 xb = __ldcs(((const float4*)v2) + (size_t)(t * BB + b) * (CC / 4) + tid);
        float u1 = sW1[i];
        float u2 = sW2[i];
        A1.x = fmaf(u1, xa.x, A1.x); A1.y = fmaf(u1, xa.y, A1.y);
        A1.z = fmaf(u1, xa.z, A1.z); A1.w = fmaf(u1, xa.w, A1.w);
        A2.x = fmaf(u2, xb.x, A2.x); A2.y = fmaf(u2, xb.y, A2.y);
        A2.z = fmaf(u2, xb.z, A2.z); A2.w = fmaf(u2, xb.w, A2.w);
    }
    ((float4*)g_pacc1)[(size_t)bid * (CC / 4) + tid] = A1;
    ((float4*)g_pacc2)[(size_t)bid * (CC / 4) + tid] = A2;
}

// ============ kernel 3a: combine stage 1 ============
// grid = BB*NSL blocks, 128 thr. Block (b, slice s): features [s*128, s*128+128).
// Thread owns one feature; sums over NC chunks x 2 paths with coalesced loads.
// Writes combined x and per-block LN partials (sum, sumsq).
__global__ void __launch_bounds__(128) k_comb1(void) {
    __shared__ float sf1[NC], sf2[NC], sS[2];
    __shared__ float red[8];

    int b = blockIdx.x >> 3;          // / NSL
    int s = blockIdx.x & (NSL - 1);
    int tid = threadIdx.x;
    int lane = tid & 31;
    int warp = tid >> 5;

    // chunk weights (warp 0; NC == 16 <= 32 lanes)
    if (warp == 0) {
        float4 pm = make_float4(-3.0e38f, -3.0e38f, 0.f, 0.f);
        if (lane < NC) pm = *(const float4*)(g_pm + (b * NC + lane) * 4);
        float M1 = pm.x, M2 = pm.y;
#pragma unroll
        for (int o = 16; o > 0; o >>= 1) {
            M1 = fmaxf(M1, __shfl_xor_sync(0xffffffffu, M1, o));
            M2 = fmaxf(M2, __shfl_xor_sync(0xffffffffu, M2, o));
        }
        float f1 = 0.f, f2 = 0.f;
        if (lane < NC) {
            f1 = expf(pm.x - M1);
            f2 = expf(pm.y - M2);
            sf1[lane] = f1;
            sf2[lane] = f2;
        }
        float t1 = pm.z * f1, t2 = pm.w * f2;
#pragma unroll
        for (int o = 16; o > 0; o >>= 1) {
            t1 += __shfl_xor_sync(0xffffffffu, t1, o);
            t2 += __shfl_xor_sync(0xffffffffu, t2, o);
        }
        if (lane == 0) { sS[0] = t1; sS[1] = t2; }
    }
    __syncthreads();

    float i1 = 1.f / sS[0];
    float i2 = 1.f / sS[1];

    int f = s * SLW + tid;            // feature index
    float x = 0.f;
#pragma unroll
    for (int c = 0; c < NC; c++) {
        float p1 = g_pacc1[(size_t)(b * NC + c) * CC + f];
        float p2 = g_pacc2[(size_t)(b * NC + c) * CC + f];
        x += sf1[c] * i1 * p1 + sf2[c] * i2 * p2;
    }
    g_x[b * CC + f] = x;

    // LN partials: sum and sumsq over this slice
    float sv = x, sq = x * x;
#pragma unroll
    for (int o = 16; o > 0; o >>= 1) {
        sv += __shfl_xor_sync(0xffffffffu, sv, o);
        sq += __shfl_xor_sync(0xffffffffu, sq, o);
    }
    if (lane == 0) { red[warp] = sv; red[4 + warp] = sq; }
    __syncthreads();
    if (tid == 0) {
        float ts = red[0] + red[1] + red[2] + red[3];
        float tq = red[4] + red[5] + red[6] + red[7];
        g_lnp[(b * NSL + s) * 2 + 0] = ts;
        g_lnp[(b * NSL + s) * 2 + 1] = tq;
    }
}

// ============ kernel 3b: combine stage 2 — LayerNorm ============
__global__ void __launch_bounds__(256) k_comb2(
    const float* __restrict__ ln_g, const float* __restrict__ ln_b,
    float* __restrict__ out) {
    __shared__ float sMu[2];
    int b = blockIdx.x;
    int tid = threadIdx.x;

    if (tid == 0) {
        float ts = 0.f, tq = 0.f;
#pragma unroll
        for (int s = 0; s < NSL; s++) {
            ts += g_lnp[(b * NSL + s) * 2 + 0];
            tq += g_lnp[(b * NSL + s) * 2 + 1];
        }
        float mu = ts * (1.f / (float)CC);
        float var = tq * (1.f / (float)CC) - mu * mu;
        sMu[0] = mu;
        sMu[1] = rsqrtf(var + 1e-6f);
    }
    __syncthreads();

    float mu = sMu[0];
    float inv = sMu[1];

    float4 x = ((const float4*)g_x)[b * (CC / 4) + tid];
    int d = tid * 4;
    float4 g = *(const float4*)(ln_g + d);
    float4 bb = *(const float4*)(ln_b + d);
    float4 o;
    o.x = (x.x - mu) * inv * g.x + bb.x;
    o.y = (x.y - mu) * inv * g.y + bb.y;
    o.z = (x.z - mu) * inv * g.z + bb.z;
    o.w = (x.w - mu) * inv * g.w + bb.w;
    *(float4*)(out + b * CC + d) = o;
}

// ---------------- launch ----------------
extern "C" void kernel_launch(void* const* d_in, const int* in_sizes, int n_in,
                              void* d_out, int out_size) {
    const float* q1     = (const float*)d_in[0];
    const float* k1     = (const float*)d_in[1];
    const float* v1     = (const float*)d_in[2];
    const float* q2     = (const float*)d_in[3];
    const float* k2     = (const float*)d_in[4];
    const float* v2     = (const float*)d_in[5];
    const float* k_mask = (const float*)d_in[6];
    const float* sa_w   = (const float*)d_in[7];
    const float* sa_b   = (const float*)d_in[8];
    const float* a1_w   = (const float*)d_in[9];
    // d_in[10] = a1_b : constant shift, cancels in softmax — unused
    const float* qk_w   = (const float*)d_in[11];
    const float* qk_b   = (const float*)d_in[12];
    const float* ln_g   = (const float*)d_in[13];
    const float* ln_b   = (const float*)d_in[14];
    float* out = (float*)d_out;

    k_rowgemm<<<1024, 256>>>(q1, q2, sa_w, qk_w);
    k_wcombine<<<512, 256>>>(sa_b, qk_b);
    k_fused<<<BB * NC, 256>>>(k1, k2, v1, v2, a1_w, k_mask);
    k_comb1<<<BB * NSL, 128>>>();
    k_comb2<<<BB, 256>>>(ln_g, ln_b, out);
}

// round 9
// speedup vs baseline: 2.2279x; 1.0208x over previous
#include <cuda_runtime.h>
#include <math.h>

#define TT   1024
#define BB   32
#define CC   1024
#define KWW  3
#define NC   16      // t-chunks in fused pass
#define TC   64      // t per chunk (NC*TC == TT)
#define KS   4       // k-splits in rowgemm
#define KSL  256     // k per split
#define NSL  16      // feature slices in combine stage 1
#define SLW  64      // features per slice (NSL*SLW == CC)

// ---------------- scratch ----------------
__device__ __align__(16) float g_wp[KS][4096 * BB];     // rowgemm partials
__device__ __align__(16) float g_saq[BB * CC];          // sa(q1) [b][c]
__device__ __align__(16) float g_ker[BB * KWW * CC];    // kernels [b][w][c]
__device__ __align__(16) float g_pm[BB * NC * 4];       // per chunk: m1,m2,ws1,ws2
__device__ __align__(16) float g_pacc1[BB * NC * CC];   // chunk partial acc path1
__device__ __align__(16) float g_pacc2[BB * NC * CC];   // chunk partial acc path2
__device__ __align__(16) float g_x[BB * CC];            // combined attend (pre-LN)
__device__ __align__(16) float g_lnp[BB * NSL * 2];     // LN partials (sum, sumsq)

__device__ __forceinline__ float tanh_approx(float x) {
    float y;
    asm("tanh.approx.f32 %0, %1;" : "=f"(y) : "f"(x));
    return y;
}

// ============ kernel 1: row GEMMs, coalesced-W ============
__global__ void __launch_bounds__(256) k_rowgemm(
    const float* __restrict__ q1, const float* __restrict__ q2,
    const float* __restrict__ sa_w, const float* __restrict__ qk_w) {
    __shared__ __align__(16) float4 qs4[BB * (KSL / 4)];   // [b][k4], 32 KB

    int tid  = threadIdx.x;
    int warp = tid >> 5;
    int lane = tid & 31;

    int ks = blockIdx.x & (KS - 1);
    int rb = blockIdx.x >> 2;              // 0..255
    bool is_sa = rb < 64;
    int r0 = rb * 16 + warp * 2;           // global row (0..4095)
    int rw = is_sa ? r0 : r0 - 1024;

    const float* q = is_sa ? q1 : q2;
    const float* W = is_sa ? sa_w : qk_w;

    {
        int k04 = ks * (KSL / 4);
#pragma unroll
        for (int i = 0; i < 8; i++) {
            int idx = i * 256 + tid;
            int b   = idx >> 6;
            int kl4 = idx & 63;
            qs4[idx] = ((const float4*)q)[b * (CC / 4) + k04 + kl4];
        }
    }
    __syncthreads();

    float acc0[32], acc1[32];
#pragma unroll
    for (int b = 0; b < 32; b++) { acc0[b] = 0.f; acc1[b] = 0.f; }

    const float4* w0p = (const float4*)(W + (size_t)rw * CC);
    const float4* w1p = (const float4*)(W + (size_t)(rw + 1) * CC);
    int k04 = ks * (KSL / 4);

#pragma unroll
    for (int j = 0; j < 2; j++) {
        float4 w0 = w0p[k04 + j * 32 + lane];
        float4 w1 = w1p[k04 + j * 32 + lane];
#pragma unroll
        for (int b = 0; b < 32; b++) {
            float4 qv = qs4[b * 64 + j * 32 + lane];
            acc0[b] = fmaf(w0.x, qv.x, acc0[b]);
            acc0[b] = fmaf(w0.y, qv.y, acc0[b]);
            acc0[b] = fmaf(w0.z, qv.z, acc0[b]);
            acc0[b] = fmaf(w0.w, qv.w, acc0[b]);
            acc1[b] = fmaf(w1.x, qv.x, acc1[b]);
            acc1[b] = fmaf(w1.y, qv.y, acc1[b]);
            acc1[b] = fmaf(w1.z, qv.z, acc1[b]);
            acc1[b] = fmaf(w1.w, qv.w, acc1[b]);
        }
    }

#pragma unroll
    for (int b = 0; b < 32; b++) {
#pragma unroll
        for (int o = 16; o > 0; o >>= 1) {
            acc0[b] += __shfl_xor_sync(0xffffffffu, acc0[b], o);
            acc1[b] += __shfl_xor_sync(0xffffffffu, acc1[b], o);
        }
    }
#pragma unroll
    for (int b = 0; b < 32; b++) {
        if (lane == b) {
            g_wp[ks][r0 * 32 + b]       = acc0[b];
            g_wp[ks][(r0 + 1) * 32 + b] = acc1[b];
        }
    }
}

// ============ kernel 1b: sum k-splits + bias, scatter ============
__global__ void __launch_bounds__(256) k_wcombine(
    const float* __restrict__ sa_b, const float* __restrict__ qk_b) {
    int idx = blockIdx.x * 256 + threadIdx.x;
    int row = idx >> 5;
    int b   = idx & 31;
    float v = g_wp[0][idx] + g_wp[1][idx] + g_wp[2][idx] + g_wp[3][idx];
    if (row < 1024) {
        g_saq[b * CC + row] = v + sa_b[row];
    } else {
        int r = row - 1024;
        int c = r / KWW;
        int w = r - c * KWW;
        g_ker[(b * KWW + w) * CC + c] = v + qk_b[r];
    }
}

// ---------------- dual block reduction ----------------
__device__ __forceinline__ void bred2(float& v1, float& v2, float* sm, int sum_mode) {
    int lane = threadIdx.x & 31;
    int warp = threadIdx.x >> 5;
#pragma unroll
    for (int o = 16; o > 0; o >>= 1) {
        float o1 = __shfl_xor_sync(0xffffffffu, v1, o);
        float o2 = __shfl_xor_sync(0xffffffffu, v2, o);
        if (sum_mode) { v1 += o1; v2 += o2; }
        else          { v1 = fmaxf(v1, o1); v2 = fmaxf(v2, o2); }
    }
    if (lane == 0) { sm[warp] = v1; sm[8 + warp] = v2; }
    __syncthreads();
    float a = sm[lane & 7], b = sm[8 + (lane & 7)];
#pragma unroll
    for (int o = 4; o > 0; o >>= 1) {
        float oa = __shfl_xor_sync(0xffffffffu, a, o);
        float ob = __shfl_xor_sync(0xffffffffu, b, o);
        if (sum_mode) { a += oa; b += ob; }
        else          { a = fmaxf(a, oa); b = fmaxf(b, ob); }
    }
    v1 = __shfl_sync(0xffffffffu, a, 0);
    v2 = __shfl_sync(0xffffffffu, b, 0);
    __syncthreads();
}

// ============ kernel 2: fused flash pass (TC=64, NC=16) ============
__global__ void __launch_bounds__(256) k_fused(
    const float* __restrict__ k1, const float* __restrict__ k2,
    const float* __restrict__ v1, const float* __restrict__ v2,
    const float* __restrict__ a1w, const float* __restrict__ k_mask) {
    __shared__ __align__(16) float s_sq[CC], s_aw[CC], s_r0[CC], s_r1[CC], s_r2[CC];
    __shared__ float sA1[TC], sS0[TC], sS1[TC], sS2[TC], sW1[TC], sW2[TC];
    __shared__ float sEdge[2];
    __shared__ float sm[16];

    int bid = blockIdx.x;
    int b  = bid >> 4;
    int c  = bid & (NC - 1);
    int t0 = c * TC;
    int tid = threadIdx.x;
    int warp = tid >> 5;
    int lane = tid & 31;

    {
        int i = tid;
        ((float4*)s_sq)[i] = ((const float4*)(g_saq + b * CC))[i];
        ((float4*)s_aw)[i] = ((const float4*)a1w)[i];
        ((float4*)s_r0)[i] = ((const float4*)(g_ker + (b * KWW + 0) * CC))[i];
        ((float4*)s_r1)[i] = ((const float4*)(g_ker + (b * KWW + 1) * CC))[i];
        ((float4*)s_r2)[i] = ((const float4*)(g_ker + (b * KWW + 2) * CC))[i];
    }
    __syncthreads();

#pragma unroll
    for (int it = 0; it < TC / 8; ++it) {
        int i = it * 8 + warp;
        int t = t0 + i;
        const float4* k1p = (const float4*)(k1 + (size_t)(t * BB + b) * CC);
        const float4* k2p = (const float4*)(k2 + (size_t)(t * BB + b) * CC);

        float a1 = 0.f, s0 = 0.f, s1 = 0.f, s2 = 0.f;
#pragma unroll
        for (int q = 0; q < 8; q++) {
            int c4 = q * 32 + lane;
            float4 x1 = __ldcs(k1p + c4);      // streaming: read-once data
            float4 x2 = __ldcs(k2p + c4);
            float4 sv = ((const float4*)s_sq)[c4];
            float4 av = ((const float4*)s_aw)[c4];
            float4 r0 = ((const float4*)s_r0)[c4];
            float4 r1 = ((const float4*)s_r1)[c4];
            float4 r2 = ((const float4*)s_r2)[c4];

            a1 = fmaf(tanh_approx(sv.x + x1.x), av.x, a1);
            a1 = fmaf(tanh_approx(sv.y + x1.y), av.y, a1);
            a1 = fmaf(tanh_approx(sv.z + x1.z), av.z, a1);
            a1 = fmaf(tanh_approx(sv.w + x1.w), av.w, a1);

            s0 = fmaf(r0.x, x2.x, s0); s0 = fmaf(r0.y, x2.y, s0);
            s0 = fmaf(r0.z, x2.z, s0); s0 = fmaf(r0.w, x2.w, s0);
            s1 = fmaf(r1.x, x2.x, s1); s1 = fmaf(r1.y, x2.y, s1);
            s1 = fmaf(r1.z, x2.z, s1); s1 = fmaf(r1.w, x2.w, s1);
            s2 = fmaf(r2.x, x2.x, s2); s2 = fmaf(r2.y, x2.y, s2);
            s2 = fmaf(r2.z, x2.z, s2); s2 = fmaf(r2.w, x2.w, s2);
        }
#pragma unroll
        for (int o = 16; o > 0; o >>= 1) {
            a1 += __shfl_xor_sync(0xffffffffu, a1, o);
            s0 += __shfl_xor_sync(0xffffffffu, s0, o);
            s1 += __shfl_xor_sync(0xffffffffu, s1, o);
            s2 += __shfl_xor_sync(0xffffffffu, s2, o);
        }
        if (lane == 0) { sA1[i] = a1; sS0[i] = s0; sS1[i] = s1; sS2[i] = s2; }
    }

    if (warp == 0) {
        float s = 0.f;
        if (t0 > 0) {
            const float4* kp = (const float4*)(k2 + (size_t)((t0 - 1) * BB + b) * CC);
#pragma unroll
            for (int q = 0; q < 8; q++) {
                int c4 = q * 32 + lane;
                float4 x = kp[c4];
                float4 r = ((const float4*)s_r0)[c4];
                s += r.x * x.x + r.y * x.y + r.z * x.z + r.w * x.w;
            }
        }
#pragma unroll
        for (int o = 16; o > 0; o >>= 1) s += __shfl_xor_sync(0xffffffffu, s, o);
        if (lane == 0) sEdge[0] = s;
    } else if (warp == 1) {
        float s = 0.f;
        if (t0 + TC < TT) {
            const float4* kp = (const float4*)(k2 + (size_t)((t0 + TC) * BB + b) * CC);
#pragma unroll
            for (int q = 0; q < 8; q++) {
                int c4 = q * 32 + lane;
                float4 x = kp[c4];
                float4 r = ((const float4*)s_r2)[c4];
                s += r.x * x.x + r.y * x.y + r.z * x.z + r.w * x.w;
            }
        }
#pragma unroll
        for (int o = 16; o > 0; o >>= 1) s += __shfl_xor_sync(0xffffffffu, s, o);
        if (lane == 0) sEdge[1] = s;
    }
    __syncthreads();

    float a1v = -3.0e38f, a2v = -3.0e38f, mk = 0.f;
    if (tid < TC) {
        int i = tid;
        a1v = sA1[i];
        a2v = sS1[i]
            + (i > 0      ? sS0[i - 1] : sEdge[0])
            + (i < TC - 1 ? sS2[i + 1] : sEdge[1]);
        mk = k_mask[(t0 + i) * BB + b];
    }
    float m1 = a1v, m2 = a2v;
    bred2(m1, m2, sm, 0);

    float w1 = 0.f, w2 = 0.f;
    if (tid < TC) {
        w1 = expf(a1v - m1) * mk;
        w2 = expf(a2v - m2) * mk;
        sW1[tid] = w1;
        sW2[tid] = w2;
    }
    float ws1 = w1, ws2 = w2;
    bred2(ws1, ws2, sm, 1);

    if (tid == 0)
        *(float4*)(g_pm + bid * 4) = make_float4(m1, m2, ws1, ws2);
    __syncthreads();

    float4 A1 = make_float4(0.f, 0.f, 0.f, 0.f);
    float4 A2 = make_float4(0.f, 0.f, 0.f, 0.f);
#pragma unroll 4
    for (int i = 0; i < TC; i++) {
        int t = t0 + i;
        float4 xa = __ldcs(((const float4*)v1) + (size_t)(t * BB + b) * (CC / 4) + tid);
        float4 xb = __ldcs(((const float4*)v2) + (size_t)(t * BB + b) * (CC / 4) + tid);
        float u1 = sW1[i];
        float u2 = sW2[i];
        A1.x = fmaf(u1, xa.x, A1.x); A1.y = fmaf(u1, xa.y, A1.y);
        A1.z = fmaf(u1, xa.z, A1.z); A1.w = fmaf(u1, xa.w, A1.w);
        A2.x = fmaf(u2, xb.x, A2.x); A2.y = fmaf(u2, xb.y, A2.y);
        A2.z = fmaf(u2, xb.z, A2.z); A2.w = fmaf(u2, xb.w, A2.w);
    }
    ((float4*)g_pacc1)[(size_t)bid * (CC / 4) + tid] = A1;
    ((float4*)g_pacc2)[(size_t)bid * (CC / 4) + tid] = A2;
}

// ============ kernel 3a: combine stage 1 (high-occupancy) ============
// grid = BB*NSL = 512 blocks, 256 thr. Block (b, slice s): 64 features (16 float4).
// tid = chunk*16 + f4slot: each thread loads ONE chunk's float4 from both paths,
// applies normalized chunk weight, tree-reduces the 16 chunks in smem.
__global__ void __launch_bounds__(256) k_comb1(void) {
    __shared__ float sf1[NC], sf2[NC], sS[2];
    __shared__ __align__(16) float4 sred[256];

    int b = blockIdx.x >> 4;          // / NSL
    int s = blockIdx.x & (NSL - 1);
    int tid = threadIdx.x;
    int lane = tid & 31;
    int warp = tid >> 5;

    int ch  = tid >> 4;               // chunk 0..15
    int f4i = tid & 15;               // float4 slot 0..15

    // issue the two loads early (independent of weights)
    size_t base = (size_t)(b * NC + ch) * (CC / 4) + s * (SLW / 4) + f4i;
    float4 p1 = __ldcs(((const float4*)g_pacc1) + base);
    float4 p2 = __ldcs(((const float4*)g_pacc2) + base);

    // chunk weights (warp 0; NC == 16 <= 32 lanes)
    if (warp == 0) {
        float4 pm = make_float4(-3.0e38f, -3.0e38f, 0.f, 0.f);
        if (lane < NC) pm = *(const float4*)(g_pm + (b * NC + lane) * 4);
        float M1 = pm.x, M2 = pm.y;
#pragma unroll
        for (int o = 16; o > 0; o >>= 1) {
            M1 = fmaxf(M1, __shfl_xor_sync(0xffffffffu, M1, o));
            M2 = fmaxf(M2, __shfl_xor_sync(0xffffffffu, M2, o));
        }
        float f1 = 0.f, f2 = 0.f;
        if (lane < NC) {
            f1 = expf(pm.x - M1);
            f2 = expf(pm.y - M2);
            sf1[lane] = f1;
            sf2[lane] = f2;
        }
        float t1 = pm.z * f1, t2 = pm.w * f2;
#pragma unroll
        for (int o = 16; o > 0; o >>= 1) {
            t1 += __shfl_xor_sync(0xffffffffu, t1, o);
            t2 += __shfl_xor_sync(0xffffffffu, t2, o);
        }
        if (lane == 0) { sS[0] = t1; sS[1] = t2; }
    }
    __syncthreads();

    float w1 = sf1[ch] / sS[0];
    float w2 = sf2[ch] / sS[1];

    float4 x;
    x.x = w1 * p1.x + w2 * p2.x;
    x.y = w1 * p1.y + w2 * p2.y;
    x.z = w1 * p1.z + w2 * p2.z;
    x.w = w1 * p1.w + w2 * p2.w;
    sred[tid] = x;
    __syncthreads();

    // tree-reduce chunk dimension (stride 16 layout -> offsets 128,64,32,16)
#pragma unroll
    for (int o = 128; o >= 16; o >>= 1) {
        if (tid < o) {
            float4 a = sred[tid];
            float4 c = sred[tid + o];
            a.x += c.x; a.y += c.y; a.z += c.z; a.w += c.w;
            sred[tid] = a;
        }
        __syncthreads();
    }

    if (tid < 16) {
        float4 v = sred[tid];
        ((float4*)g_x)[b * (CC / 4) + s * (SLW / 4) + tid] = v;

        float sv = v.x + v.y + v.z + v.w;
        float sq = v.x * v.x + v.y * v.y + v.z * v.z + v.w * v.w;
#pragma unroll
        for (int o = 8; o > 0; o >>= 1) {
            sv += __shfl_xor_sync(0x0000ffffu, sv, o);
            sq += __shfl_xor_sync(0x0000ffffu, sq, o);
        }
        if (tid == 0) {
            g_lnp[(b * NSL + s) * 2 + 0] = sv;
            g_lnp[(b * NSL + s) * 2 + 1] = sq;
        }
    }
}

// ============ kernel 3b: combine stage 2 — LayerNorm ============
__global__ void __launch_bounds__(256) k_comb2(
    const float* __restrict__ ln_g, const float* __restrict__ ln_b,
    float* __restrict__ out) {
    __shared__ float sMu[2];
    int b = blockIdx.x;
    int tid = threadIdx.x;

    if (tid == 0) {
        float ts = 0.f, tq = 0.f;
#pragma unroll
        for (int s = 0; s < NSL; s++) {
            ts += g_lnp[(b * NSL + s) * 2 + 0];
            tq += g_lnp[(b * NSL + s) * 2 + 1];
        }
        float mu = ts * (1.f / (float)CC);
        float var = tq * (1.f / (float)CC) - mu * mu;
        sMu[0] = mu;
        sMu[1] = rsqrtf(var + 1e-6f);
    }
    __syncthreads();

    float mu = sMu[0];
    float inv = sMu[1];

    float4 x = ((const float4*)g_x)[b * (CC / 4) + tid];
    int d = tid * 4;
    float4 g = *(const float4*)(ln_g + d);
    float4 bb = *(const float4*)(ln_b + d);
    float4 o;
    o.x = (x.x - mu) * inv * g.x + bb.x;
    o.y = (x.y - mu) * inv * g.y + bb.y;
    o.z = (x.z - mu) * inv * g.z + bb.z;
    o.w = (x.w - mu) * inv * g.w + bb.w;
    *(float4*)(out + b * CC + d) = o;
}

// ---------------- launch ----------------
extern "C" void kernel_launch(void* const* d_in, const int* in_sizes, int n_in,
                              void* d_out, int out_size) {
    const float* q1     = (const float*)d_in[0];
    const float* k1     = (const float*)d_in[1];
    const float* v1     = (const float*)d_in[2];
    const float* q2     = (const float*)d_in[3];
    const float* k2     = (const float*)d_in[4];
    const float* v2     = (const float*)d_in[5];
    const float* k_mask = (const float*)d_in[6];
    const float* sa_w   = (const float*)d_in[7];
    const float* sa_b   = (const float*)d_in[8];
    const float* a1_w   = (const float*)d_in[9];
    // d_in[10] = a1_b : constant shift, cancels in softmax — unused
    const float* qk_w   = (const float*)d_in[11];
    const float* qk_b   = (const float*)d_in[12];
    const float* ln_g   = (const float*)d_in[13];
    const float* ln_b   = (const float*)d_in[14];
    float* out = (float*)d_out;

    k_rowgemm<<<1024, 256>>>(q1, q2, sa_w, qk_w);
    k_wcombine<<<512, 256>>>(sa_b, qk_b);
    k_fused<<<BB * NC, 256>>>(k1, k2, v1, v2, a1_w, k_mask);
    k_comb1<<<BB * NSL, 256>>>();
    k_comb2<<<BB, 256>>>(ln_g, ln_b, out);
}

// round 12
// speedup vs baseline: 2.4480x; 1.0988x over previous
#include <cuda_runtime.h>
#include <math.h>

#define TT   1024
#define BB   32
#define CC   1024
#define KWW  3
#define NC   16      // t-chunks in fused pass
#define TC   64      // t per chunk (NC*TC == TT)
#define KSL  256     // k per staging chunk in rowgemm
#define NSL  16      // feature slices in combine stage 1
#define SLW  64      // features per slice (NSL*SLW == CC)

// ---------------- scratch ----------------
__device__ __align__(16) float g_saq[BB * CC];          // sa(q1) [b][c]
__device__ __align__(16) float g_ker[BB * KWW * CC];    // kernels [b][w][c]
__device__ __align__(16) float g_pm[BB * NC * 4];       // per chunk: m1,m2,ws1,ws2
__device__ __align__(16) float g_pacc1[BB * NC * CC];   // chunk partial acc path1
__device__ __align__(16) float g_pacc2[BB * NC * CC];   // chunk partial acc path2
__device__ __align__(16) float g_x[BB * CC];            // combined attend (pre-LN)
__device__ __align__(16) float g_lnp[BB * NSL * 2];     // LN partials (sum, sumsq)

__device__ __forceinline__ float tanh_approx(float x) {
    float y;
    asm("tanh.approx.f32 %0, %1;" : "=f"(y) : "f"(x));
    return y;
}

// ============ kernel 1: row GEMMs, coalesced-W, full-K (no split) ============
// grid 256 blocks x 256 thr. Block = 16 rows; warp = 2 rows; lane owns a
// consecutive float4 of W (coalesced LDG.128). q staged per 256-k chunk in smem
// [b][k4] (conflict-free LDS.128). Butterfly reduce + bias + scatter in tail.
__global__ void __launch_bounds__(256) k_rowgemm(
    const float* __restrict__ q1, const float* __restrict__ q2,
    const float* __restrict__ sa_w, const float* __restrict__ qk_w,
    const float* __restrict__ sa_b, const float* __restrict__ qk_b) {
    __shared__ __align__(16) float4 qs4[BB * (KSL / 4)];   // [b][k4], 32 KB

    int tid  = threadIdx.x;
    int warp = tid >> 5;
    int lane = tid & 31;

    int rb = blockIdx.x;                   // 0..255
    bool is_sa = rb < 64;
    int r0 = rb * 16 + warp * 2;           // global row (0..4095)
    int rw = is_sa ? r0 : r0 - 1024;

    const float* q = is_sa ? q1 : q2;
    const float* W = is_sa ? sa_w : qk_w;
    const float* Bi = is_sa ? sa_b : qk_b;
    int rwb = is_sa ? r0 : r0 - 1024;      // row within bias vector

    const float4* w0p = (const float4*)(W + (size_t)rw * CC);
    const float4* w1p = (const float4*)(W + (size_t)(rw + 1) * CC);

    float acc0[32], acc1[32];
#pragma unroll
    for (int b = 0; b < 32; b++) { acc0[b] = 0.f; acc1[b] = 0.f; }

    for (int chunk = 0; chunk < 4; chunk++) {
        int k04 = chunk * (KSL / 4);
        if (chunk) __syncthreads();        // protect previous chunk's smem
        {
#pragma unroll
            for (int i = 0; i < 8; i++) {
                int idx = i * 256 + tid;   // 0..2047
                int b   = idx >> 6;
                int kl4 = idx & 63;
                qs4[idx] = ((const float4*)q)[b * (CC / 4) + k04 + kl4];
            }
        }
        __syncthreads();

#pragma unroll
        for (int j = 0; j < 2; j++) {
            float4 w0 = w0p[k04 + j * 32 + lane];
            float4 w1 = w1p[k04 + j * 32 + lane];
#pragma unroll
            for (int b = 0; b < 32; b++) {
                float4 qv = qs4[b * 64 + j * 32 + lane];
                acc0[b] = fmaf(w0.x, qv.x, acc0[b]);
                acc0[b] = fmaf(w0.y, qv.y, acc0[b]);
                acc0[b] = fmaf(w0.z, qv.z, acc0[b]);
                acc0[b] = fmaf(w0.w, qv.w, acc0[b]);
                acc1[b] = fmaf(w1.x, qv.x, acc1[b]);
                acc1[b] = fmaf(w1.y, qv.y, acc1[b]);
                acc1[b] = fmaf(w1.z, qv.z, acc1[b]);
                acc1[b] = fmaf(w1.w, qv.w, acc1[b]);
            }
        }
    }

#pragma unroll
    for (int b = 0; b < 32; b++) {
#pragma unroll
        for (int o = 16; o > 0; o >>= 1) {
            acc0[b] += __shfl_xor_sync(0xffffffffu, acc0[b], o);
            acc1[b] += __shfl_xor_sync(0xffffffffu, acc1[b], o);
        }
    }

    float b0 = Bi[rwb];
    float b1 = Bi[rwb + 1];
#pragma unroll
    for (int b = 0; b < 32; b++) {
        if (lane == b) {
            float v0 = acc0[b] + b0;
            float v1 = acc1[b] + b1;
            if (is_sa) {
                g_saq[b * CC + r0]     = v0;
                g_saq[b * CC + r0 + 1] = v1;
            } else {
                int rr0 = r0 - 1024;
                int c0 = rr0 / KWW, w0i = rr0 - c0 * KWW;
                int rr1 = rr0 + 1;
                int c1 = rr1 / KWW, w1i = rr1 - c1 * KWW;
                g_ker[(b * KWW + w0i) * CC + c0] = v0;
                g_ker[(b * KWW + w1i) * CC + c1] = v1;
            }
        }
    }
}

// ---------------- dual block reduction ----------------
__device__ __forceinline__ void bred2(float& v1, float& v2, float* sm, int sum_mode) {
    int lane = threadIdx.x & 31;
    int warp = threadIdx.x >> 5;
#pragma unroll
    for (int o = 16; o > 0; o >>= 1) {
        float o1 = __shfl_xor_sync(0xffffffffu, v1, o);
        float o2 = __shfl_xor_sync(0xffffffffu, v2, o);
        if (sum_mode) { v1 += o1; v2 += o2; }
        else          { v1 = fmaxf(v1, o1); v2 = fmaxf(v2, o2); }
    }
    if (lane == 0) { sm[warp] = v1; sm[8 + warp] = v2; }
    __syncthreads();
    float a = sm[lane & 7], b = sm[8 + (lane & 7)];
#pragma unroll
    for (int o = 4; o > 0; o >>= 1) {
        float oa = __shfl_xor_sync(0xffffffffu, a, o);
        float ob = __shfl_xor_sync(0xffffffffu, b, o);
        if (sum_mode) { a += oa; b += ob; }
        else          { a = fmaxf(a, oa); b = fmaxf(b, ob); }
    }
    v1 = __shfl_sync(0xffffffffu, a, 0);
    v2 = __shfl_sync(0xffffffffu, b, 0);
    __syncthreads();
}

// ============ kernel 2: fused flash pass (TC=64, NC=16) — frozen R8/R9 winner ============
__global__ void __launch_bounds__(256) k_fused(
    const float* __restrict__ k1, const float* __restrict__ k2,
    const float* __restrict__ v1, const float* __restrict__ v2,
    const float* __restrict__ a1w, const float* __restrict__ k_mask) {
    __shared__ __align__(16) float s_sq[CC], s_aw[CC], s_r0[CC], s_r1[CC], s_r2[CC];
    __shared__ float sA1[TC], sS0[TC], sS1[TC], sS2[TC], sW1[TC], sW2[TC];
    __shared__ float sEdge[2];
    __shared__ float sm[16];

    int bid = blockIdx.x;
    int b  = bid >> 4;
    int c  = bid & (NC - 1);
    int t0 = c * TC;
    int tid = threadIdx.x;
    int warp = tid >> 5;
    int lane = tid & 31;

    {
        int i = tid;
        ((float4*)s_sq)[i] = ((const float4*)(g_saq + b * CC))[i];
        ((float4*)s_aw)[i] = ((const float4*)a1w)[i];
        ((float4*)s_r0)[i] = ((const float4*)(g_ker + (b * KWW + 0) * CC))[i];
        ((float4*)s_r1)[i] = ((const float4*)(g_ker + (b * KWW + 1) * CC))[i];
        ((float4*)s_r2)[i] = ((const float4*)(g_ker + (b * KWW + 2) * CC))[i];
    }
    __syncthreads();

#pragma unroll
    for (int it = 0; it < TC / 8; ++it) {
        int i = it * 8 + warp;
        int t = t0 + i;
        const float4* k1p = (const float4*)(k1 + (size_t)(t * BB + b) * CC);
        const float4* k2p = (const float4*)(k2 + (size_t)(t * BB + b) * CC);

        float a1 = 0.f, s0 = 0.f, s1 = 0.f, s2 = 0.f;
#pragma unroll
        for (int q = 0; q < 8; q++) {
            int c4 = q * 32 + lane;
            float4 x1 = __ldcs(k1p + c4);      // streaming: read-once data
            float4 x2 = __ldcs(k2p + c4);
            float4 sv = ((const float4*)s_sq)[c4];
            float4 av = ((const float4*)s_aw)[c4];
            float4 r0 = ((const float4*)s_r0)[c4];
            float4 r1 = ((const float4*)s_r1)[c4];
            float4 r2 = ((const float4*)s_r2)[c4];

            a1 = fmaf(tanh_approx(sv.x + x1.x), av.x, a1);
            a1 = fmaf(tanh_approx(sv.y + x1.y), av.y, a1);
            a1 = fmaf(tanh_approx(sv.z + x1.z), av.z, a1);
            a1 = fmaf(tanh_approx(sv.w + x1.w), av.w, a1);

            s0 = fmaf(r0.x, x2.x, s0); s0 = fmaf(r0.y, x2.y, s0);
            s0 = fmaf(r0.z, x2.z, s0); s0 = fmaf(r0.w, x2.w, s0);
            s1 = fmaf(r1.x, x2.x, s1); s1 = fmaf(r1.y, x2.y, s1);
            s1 = fmaf(r1.z, x2.z, s1); s1 = fmaf(r1.w, x2.w, s1);
            s2 = fmaf(r2.x, x2.x, s2); s2 = fmaf(r2.y, x2.y, s2);
            s2 = fmaf(r2.z, x2.z, s2); s2 = fmaf(r2.w, x2.w, s2);
        }
#pragma unroll
        for (int o = 16; o > 0; o >>= 1) {
            a1 += __shfl_xor_sync(0xffffffffu, a1, o);
            s0 += __shfl_xor_sync(0xffffffffu, s0, o);
            s1 += __shfl_xor_sync(0xffffffffu, s1, o);
            s2 += __shfl_xor_sync(0xffffffffu, s2, o);
        }
        if (lane == 0) { sA1[i] = a1; sS0[i] = s0; sS1[i] = s1; sS2[i] = s2; }
    }

    if (warp == 0) {
        float s = 0.f;
        if (t0 > 0) {
            const float4* kp = (const float4*)(k2 + (size_t)((t0 - 1) * BB + b) * CC);
#pragma unroll
            for (int q = 0; q < 8; q++) {
                int c4 = q * 32 + lane;
                float4 x = kp[c4];
                float4 r = ((const float4*)s_r0)[c4];
                s += r.x * x.x + r.y * x.y + r.z * x.z + r.w * x.w;
            }
        }
#pragma unroll
        for (int o = 16; o > 0; o >>= 1) s += __shfl_xor_sync(0xffffffffu, s, o);
        if (lane == 0) sEdge[0] = s;
    } else if (warp == 1) {
        float s = 0.f;
        if (t0 + TC < TT) {
            const float4* kp = (const float4*)(k2 + (size_t)((t0 + TC) * BB + b) * CC);
#pragma unroll
            for (int q = 0; q < 8; q++) {
                int c4 = q * 32 + lane;
                float4 x = kp[c4];
                float4 r = ((const float4*)s_r2)[c4];
                s += r.x * x.x + r.y * x.y + r.z * x.z + r.w * x.w;
            }
        }
#pragma unroll
        for (int o = 16; o > 0; o >>= 1) s += __shfl_xor_sync(0xffffffffu, s, o);
        if (lane == 0) sEdge[1] = s;
    }
    __syncthreads();

    float a1v = -3.0e38f, a2v = -3.0e38f, mk = 0.f;
    if (tid < TC) {
        int i = tid;
        a1v = sA1[i];
        a2v = sS1[i]
            + (i > 0      ? sS0[i - 1] : sEdge[0])
            + (i < TC - 1 ? sS2[i + 1] : sEdge[1]);
        mk = k_mask[(t0 + i) * BB + b];
    }
    float m1 = a1v, m2 = a2v;
    bred2(m1, m2, sm, 0);

    float w1 = 0.f, w2 = 0.f;
    if (tid < TC) {
        w1 = expf(a1v - m1) * mk;
        w2 = expf(a2v - m2) * mk;
        sW1[tid] = w1;
        sW2[tid] = w2;
    }
    float ws1 = w1, ws2 = w2;
    bred2(ws1, ws2, sm, 1);

    if (tid == 0)
        *(float4*)(g_pm + bid * 4) = make_float4(m1, m2, ws1, ws2);
    __syncthreads();

    float4 A1 = make_float4(0.f, 0.f, 0.f, 0.f);
    float4 A2 = make_float4(0.f, 0.f, 0.f, 0.f);
#pragma unroll 4
    for (int i = 0; i < TC; i++) {
        int t = t0 + i;
        float4 xa = __ldcs(((const float4*)v1) + (size_t)(t * BB + b) * (CC / 4) + tid);
        float4 xb = __ldcs(((const float4*)v2) + (size_t)(t * BB + b) * (CC / 4) + tid);
        float u1 = sW1[i];
        float u2 = sW2[i];
        A1.x = fmaf(u1, xa.x, A1.x); A1.y = fmaf(u1, xa.y, A1.y);
        A1.z = fmaf(u1, xa.z, A1.z); A1.w = fmaf(u1, xa.w, A1.w);
        A2.x = fmaf(u2, xb.x, A2.x); A2.y = fmaf(u2, xb.y, A2.y);
        A2.z = fmaf(u2, xb.z, A2.z); A2.w = fmaf(u2, xb.w, A2.w);
    }
    ((float4*)g_pacc1)[(size_t)bid * (CC / 4) + tid] = A1;
    ((float4*)g_pacc2)[(size_t)bid * (CC / 4) + tid] = A2;
}

// ============ kernel 3a: combine stage 1 — frozen R9 winner ============
__global__ void __launch_bounds__(256) k_comb1(void) {
    __shared__ float sf1[NC], sf2[NC], sS[2];
    __shared__ __align__(16) float4 sred[256];

    int b = blockIdx.x >> 4;          // / NSL
    int s = blockIdx.x & (NSL - 1);
    int tid = threadIdx.x;
    int lane = tid & 31;
    int warp = tid >> 5;

    int ch  = tid >> 4;               // chunk 0..15
    int f4i = tid & 15;               // float4 slot 0..15

    size_t base = (size_t)(b * NC + ch) * (CC / 4) + s * (SLW / 4) + f4i;
    float4 p1 = __ldcs(((const float4*)g_pacc1) + base);
    float4 p2 = __ldcs(((const float4*)g_pacc2) + base);

    if (warp == 0) {
        float4 pm = make_float4(-3.0e38f, -3.0e38f, 0.f, 0.f);
        if (lane < NC) pm = *(const float4*)(g_pm + (b * NC + lane) * 4);
        float M1 = pm.x, M2 = pm.y;
#pragma unroll
        for (int o = 16; o > 0; o >>= 1) {
            M1 = fmaxf(M1, __shfl_xor_sync(0xffffffffu, M1, o));
            M2 = fmaxf(M2, __shfl_xor_sync(0xffffffffu, M2, o));
        }
        float f1 = 0.f, f2 = 0.f;
        if (lane < NC) {
            f1 = expf(pm.x - M1);
            f2 = expf(pm.y - M2);
            sf1[lane] = f1;
            sf2[lane] = f2;
        }
        float t1 = pm.z * f1, t2 = pm.w * f2;
#pragma unroll
        for (int o = 16; o > 0; o >>= 1) {
            t1 += __shfl_xor_sync(0xffffffffu, t1, o);
            t2 += __shfl_xor_sync(0xffffffffu, t2, o);
        }
        if (lane == 0) { sS[0] = t1; sS[1] = t2; }
    }
    __syncthreads();

    float w1 = sf1[ch] / sS[0];
    float w2 = sf2[ch] / sS[1];

    float4 x;
    x.x = w1 * p1.x + w2 * p2.x;
    x.y = w1 * p1.y + w2 * p2.y;
    x.z = w1 * p1.z + w2 * p2.z;
    x.w = w1 * p1.w + w2 * p2.w;
    sred[tid] = x;
    __syncthreads();

#pragma unroll
    for (int o = 128; o >= 16; o >>= 1) {
        if (tid < o) {
            float4 a = sred[tid];
            float4 c = sred[tid + o];
            a.x += c.x; a.y += c.y; a.z += c.z; a.w += c.w;
            sred[tid] = a;
        }
        __syncthreads();
    }

    if (tid < 16) {
        float4 v = sred[tid];
        ((float4*)g_x)[b * (CC / 4) + s * (SLW / 4) + tid] = v;

        float sv = v.x + v.y + v.z + v.w;
        float sq = v.x * v.x + v.y * v.y + v.z * v.z + v.w * v.w;
#pragma unroll
        for (int o = 8; o > 0; o >>= 1) {
            sv += __shfl_xor_sync(0x0000ffffu, sv, o);
            sq += __shfl_xor_sync(0x0000ffffu, sq, o);
        }
        if (tid == 0) {
            g_lnp[(b * NSL + s) * 2 + 0] = sv;
            g_lnp[(b * NSL + s) * 2 + 1] = sq;
        }
    }
}

// ============ kernel 3b: combine stage 2 — LayerNorm ============
__global__ void __launch_bounds__(256) k_comb2(
    const float* __restrict__ ln_g, const float* __restrict__ ln_b,
    float* __restrict__ out) {
    __shared__ float sMu[2];
    int b = blockIdx.x;
    int tid = threadIdx.x;

    if (tid == 0) {
        float ts = 0.f, tq = 0.f;
#pragma unroll
        for (int s = 0; s < NSL; s++) {
            ts += g_lnp[(b * NSL + s) * 2 + 0];
            tq += g_lnp[(b * NSL + s) * 2 + 1];
        }
        float mu = ts * (1.f / (float)CC);
        float var = tq * (1.f / (float)CC) - mu * mu;
        sMu[0] = mu;
        sMu[1] = rsqrtf(var + 1e-6f);
    }
    __syncthreads();

    float mu = sMu[0];
    float inv = sMu[1];

    float4 x = ((const float4*)g_x)[b * (CC / 4) + tid];
    int d = tid * 4;
    float4 g = *(const float4*)(ln_g + d);
    float4 bb = *(const float4*)(ln_b + d);
    float4 o;
    o.x = (x.x - mu) * inv * g.x + bb.x;
    o.y = (x.y - mu) * inv * g.y + bb.y;
    o.z = (x.z - mu) * inv * g.z + bb.z;
    o.w = (x.w - mu) * inv * g.w + bb.w;
    *(float4*)(out + b * CC + d) = o;
}

// ---------------- launch ----------------
extern "C" void kernel_launch(void* const* d_in, const int* in_sizes, int n_in,
                              void* d_out, int out_size) {
    const float* q1     = (const float*)d_in[0];
    const float* k1     = (const float*)d_in[1];
    const float* v1     = (const float*)d_in[2];
    const float* q2     = (const float*)d_in[3];
    const float* k2     = (const float*)d_in[4];
    const float* v2     = (const float*)d_in[5];
    const float* k_mask = (const float*)d_in[6];
    const float* sa_w   = (const float*)d_in[7];
    const float* sa_b   = (const float*)d_in[8];
    const float* a1_w   = (const float*)d_in[9];
    // d_in[10] = a1_b : constant shift, cancels in softmax — unused
    const float* qk_w   = (const float*)d_in[11];
    const float* qk_b   = (const float*)d_in[12];
    const float* ln_g   = (const float*)d_in[13];
    const float* ln_b   = (const float*)d_in[14];
    float* out = (float*)d_out;

    k_rowgemm<<<256, 256>>>(q1, q2, sa_w, qk_w, sa_b, qk_b);
    k_fused<<<BB * NC, 256>>>(k1, k2, v1, v2, a1_w, k_mask);
    k_comb1<<<BB * NSL, 256>>>();
    k_comb2<<<BB, 256>>>(ln_g, ln_b, out);
}

// round 13
// speedup vs baseline: 2.4854x; 1.0152x over previous
#include <cuda_runtime.h>
#include <math.h>

#define TT   1024
#define BB   32
#define CC   1024
#define KWW  3
#define NC   16      // t-chunks in fused pass
#define TC   64      // t per chunk (NC*TC == TT)
#define KSL  256     // k per staging chunk in rowgemm

// ---------------- scratch ----------------
__device__ __align__(16) float g_saq[BB * CC];          // sa(q1) [b][c]
__device__ __align__(16) float g_ker[BB * KWW * CC];    // kernels [b][w][c]
__device__ __align__(16) float g_pm[BB * NC * 4];       // per chunk: m1,m2,ws1,ws2
__device__ __align__(16) float g_pacc1[BB * NC * CC];   // chunk partial acc path1
__device__ __align__(16) float g_pacc2[BB * NC * CC];   // chunk partial acc path2
__device__ int g_cnt[BB];                                // chunk-completion counters

__device__ __forceinline__ float tanh_approx(float x) {
    float y;
    asm("tanh.approx.f32 %0, %1;" : "=f"(y) : "f"(x));
    return y;
}

// ============ kernel 1: row GEMMs, coalesced-W, full-K ============
// grid 256 x 256 thr. Block = 16 rows; warp = 2 rows; lane owns consecutive
// float4 of W. q staged per 256-k chunk in smem. Also resets g_cnt (block 0).
__global__ void __launch_bounds__(256) k_rowgemm(
    const float* __restrict__ q1, const float* __restrict__ q2,
    const float* __restrict__ sa_w, const float* __restrict__ qk_w,
    const float* __restrict__ sa_b, const float* __restrict__ qk_b) {
    __shared__ __align__(16) float4 qs4[BB * (KSL / 4)];   // [b][k4], 32 KB

    int tid  = threadIdx.x;
    int warp = tid >> 5;
    int lane = tid & 31;

    if (blockIdx.x == 0 && tid < BB) g_cnt[tid] = 0;   // reset for this launch

    int rb = blockIdx.x;                   // 0..255
    bool is_sa = rb < 64;
    int r0 = rb * 16 + warp * 2;           // global row (0..4095)
    int rw = is_sa ? r0 : r0 - 1024;

    const float* q = is_sa ? q1 : q2;
    const float* W = is_sa ? sa_w : qk_w;
    const float* Bi = is_sa ? sa_b : qk_b;

    const float4* w0p = (const float4*)(W + (size_t)rw * CC);
    const float4* w1p = (const float4*)(W + (size_t)(rw + 1) * CC);

    float acc0[32], acc1[32];
#pragma unroll
    for (int b = 0; b < 32; b++) { acc0[b] = 0.f; acc1[b] = 0.f; }

    for (int chunk = 0; chunk < 4; chunk++) {
        int k04 = chunk * (KSL / 4);
        if (chunk) __syncthreads();
#pragma unroll
        for (int i = 0; i < 8; i++) {
            int idx = i * 256 + tid;       // 0..2047
            int b   = idx >> 6;
            int kl4 = idx & 63;
            qs4[idx] = ((const float4*)q)[b * (CC / 4) + k04 + kl4];
        }
        __syncthreads();

#pragma unroll
        for (int j = 0; j < 2; j++) {
            float4 w0 = w0p[k04 + j * 32 + lane];
            float4 w1 = w1p[k04 + j * 32 + lane];
#pragma unroll
            for (int b = 0; b < 32; b++) {
                float4 qv = qs4[b * 64 + j * 32 + lane];
                acc0[b] = fmaf(w0.x, qv.x, acc0[b]);
                acc0[b] = fmaf(w0.y, qv.y, acc0[b]);
                acc0[b] = fmaf(w0.z, qv.z, acc0[b]);
                acc0[b] = fmaf(w0.w, qv.w, acc0[b]);
                acc1[b] = fmaf(w1.x, qv.x, acc1[b]);
                acc1[b] = fmaf(w1.y, qv.y, acc1[b]);
                acc1[b] = fmaf(w1.z, qv.z, acc1[b]);
                acc1[b] = fmaf(w1.w, qv.w, acc1[b]);
            }
        }
    }

#pragma unroll
    for (int b = 0; b < 32; b++) {
#pragma unroll
        for (int o = 16; o > 0; o >>= 1) {
            acc0[b] += __shfl_xor_sync(0xffffffffu, acc0[b], o);
            acc1[b] += __shfl_xor_sync(0xffffffffu, acc1[b], o);
        }
    }

    float b0 = Bi[rw];
    float b1 = Bi[rw + 1];
#pragma unroll
    for (int b = 0; b < 32; b++) {
        if (lane == b) {
            float v0 = acc0[b] + b0;
            float v1 = acc1[b] + b1;
            if (is_sa) {
                g_saq[b * CC + r0]     = v0;
                g_saq[b * CC + r0 + 1] = v1;
            } else {
                int rr0 = r0 - 1024;
                int c0 = rr0 / KWW, w0i = rr0 - c0 * KWW;
                int rr1 = rr0 + 1;
                int c1 = rr1 / KWW, w1i = rr1 - c1 * KWW;
                g_ker[(b * KWW + w0i) * CC + c0] = v0;
                g_ker[(b * KWW + w1i) * CC + c1] = v1;
            }
        }
    }
}

// ---------------- dual block reduction ----------------
__device__ __forceinline__ void bred2(float& v1, float& v2, float* sm, int sum_mode) {
    int lane = threadIdx.x & 31;
    int warp = threadIdx.x >> 5;
#pragma unroll
    for (int o = 16; o > 0; o >>= 1) {
        float o1 = __shfl_xor_sync(0xffffffffu, v1, o);
        float o2 = __shfl_xor_sync(0xffffffffu, v2, o);
        if (sum_mode) { v1 += o1; v2 += o2; }
        else          { v1 = fmaxf(v1, o1); v2 = fmaxf(v2, o2); }
    }
    if (lane == 0) { sm[warp] = v1; sm[8 + warp] = v2; }
    __syncthreads();
    float a = sm[lane & 7], b = sm[8 + (lane & 7)];
#pragma unroll
    for (int o = 4; o > 0; o >>= 1) {
        float oa = __shfl_xor_sync(0xffffffffu, a, o);
        float ob = __shfl_xor_sync(0xffffffffu, b, o);
        if (sum_mode) { a += oa; b += ob; }
        else          { a = fmaxf(a, oa); b = fmaxf(b, ob); }
    }
    v1 = __shfl_sync(0xffffffffu, a, 0);
    v2 = __shfl_sync(0xffffffffu, b, 0);
    __syncthreads();
}

// ============ kernel 2: fused flash pass + last-block combine/LN epilogue ============
__global__ void __launch_bounds__(256) k_fused(
    const float* __restrict__ k1, const float* __restrict__ k2,
    const float* __restrict__ v1, const float* __restrict__ v2,
    const float* __restrict__ a1w, const float* __restrict__ k_mask,
    const float* __restrict__ ln_g, const float* __restrict__ ln_b,
    float* __restrict__ out) {
    __shared__ __align__(16) float s_sq[CC], s_aw[CC], s_r0[CC], s_r1[CC], s_r2[CC];
    __shared__ float sA1[TC], sS0[TC], sS1[TC], sS2[TC], sW1[TC], sW2[TC];
    __shared__ float sEdge[2];
    __shared__ float sm[16];
    __shared__ float sf1[NC], sf2[NC], sS[2];
    __shared__ int s_last;

    int bid = blockIdx.x;
    int b  = bid >> 4;
    int c  = bid & (NC - 1);
    int t0 = c * TC;
    int tid = threadIdx.x;
    int warp = tid >> 5;
    int lane = tid & 31;

    {
        int i = tid;
        ((float4*)s_sq)[i] = ((const float4*)(g_saq + b * CC))[i];
        ((float4*)s_aw)[i] = ((const float4*)a1w)[i];
        ((float4*)s_r0)[i] = ((const float4*)(g_ker + (b * KWW + 0) * CC))[i];
        ((float4*)s_r1)[i] = ((const float4*)(g_ker + (b * KWW + 1) * CC))[i];
        ((float4*)s_r2)[i] = ((const float4*)(g_ker + (b * KWW + 2) * CC))[i];
    }
    __syncthreads();

    // ---- Phase A: per-row logits (warp per t) ----
#pragma unroll
    for (int it = 0; it < TC / 8; ++it) {
        int i = it * 8 + warp;
        int t = t0 + i;
        const float4* k1p = (const float4*)(k1 + (size_t)(t * BB + b) * CC);
        const float4* k2p = (const float4*)(k2 + (size_t)(t * BB + b) * CC);

        float a1 = 0.f, s0 = 0.f, s1 = 0.f, s2 = 0.f;
#pragma unroll
        for (int q = 0; q < 8; q++) {
            int c4 = q * 32 + lane;
            float4 x1 = __ldcs(k1p + c4);      // streaming: read-once data
            float4 x2 = __ldcs(k2p + c4);
            float4 sv = ((const float4*)s_sq)[c4];
            float4 av = ((const float4*)s_aw)[c4];
            float4 r0 = ((const float4*)s_r0)[c4];
            float4 r1 = ((const float4*)s_r1)[c4];
            float4 r2 = ((const float4*)s_r2)[c4];

            a1 = fmaf(tanh_approx(sv.x + x1.x), av.x, a1);
            a1 = fmaf(tanh_approx(sv.y + x1.y), av.y, a1);
            a1 = fmaf(tanh_approx(sv.z + x1.z), av.z, a1);
            a1 = fmaf(tanh_approx(sv.w + x1.w), av.w, a1);

            s0 = fmaf(r0.x, x2.x, s0); s0 = fmaf(r0.y, x2.y, s0);
            s0 = fmaf(r0.z, x2.z, s0); s0 = fmaf(r0.w, x2.w, s0);
            s1 = fmaf(r1.x, x2.x, s1); s1 = fmaf(r1.y, x2.y, s1);
            s1 = fmaf(r1.z, x2.z, s1); s1 = fmaf(r1.w, x2.w, s1);
            s2 = fmaf(r2.x, x2.x, s2); s2 = fmaf(r2.y, x2.y, s2);
            s2 = fmaf(r2.z, x2.z, s2); s2 = fmaf(r2.w, x2.w, s2);
        }
#pragma unroll
        for (int o = 16; o > 0; o >>= 1) {
            a1 += __shfl_xor_sync(0xffffffffu, a1, o);
            s0 += __shfl_xor_sync(0xffffffffu, s0, o);
            s1 += __shfl_xor_sync(0xffffffffu, s1, o);
            s2 += __shfl_xor_sync(0xffffffffu, s2, o);
        }
        if (lane == 0) { sA1[i] = a1; sS0[i] = s0; sS1[i] = s1; sS2[i] = s2; }
    }

    // boundary tap dots
    if (warp == 0) {
        float s = 0.f;
        if (t0 > 0) {
            const float4* kp = (const float4*)(k2 + (size_t)((t0 - 1) * BB + b) * CC);
#pragma unroll
            for (int q = 0; q < 8; q++) {
                int c4 = q * 32 + lane;
                float4 x = kp[c4];
                float4 r = ((const float4*)s_r0)[c4];
                s += r.x * x.x + r.y * x.y + r.z * x.z + r.w * x.w;
            }
        }
#pragma unroll
        for (int o = 16; o > 0; o >>= 1) s += __shfl_xor_sync(0xffffffffu, s, o);
        if (lane == 0) sEdge[0] = s;
    } else if (warp == 1) {
        float s = 0.f;
        if (t0 + TC < TT) {
            const float4* kp = (const float4*)(k2 + (size_t)((t0 + TC) * BB + b) * CC);
#pragma unroll
            for (int q = 0; q < 8; q++) {
                int c4 = q * 32 + lane;
                float4 x = kp[c4];
                float4 r = ((const float4*)s_r2)[c4];
                s += r.x * x.x + r.y * x.y + r.z * x.z + r.w * x.w;
            }
        }
#pragma unroll
        for (int o = 16; o > 0; o >>= 1) s += __shfl_xor_sync(0xffffffffu, s, o);
        if (lane == 0) sEdge[1] = s;
    }
    __syncthreads();

    // ---- chunk softmax stats ----
    float a1v = -3.0e38f, a2v = -3.0e38f, mk = 0.f;
    if (tid < TC) {
        int i = tid;
        a1v = sA1[i];
        a2v = sS1[i]
            + (i > 0      ? sS0[i - 1] : sEdge[0])
            + (i < TC - 1 ? sS2[i + 1] : sEdge[1]);
        mk = k_mask[(t0 + i) * BB + b];
    }
    float m1 = a1v, m2 = a2v;
    bred2(m1, m2, sm, 0);

    float w1 = 0.f, w2 = 0.f;
    if (tid < TC) {
        w1 = expf(a1v - m1) * mk;
        w2 = expf(a2v - m2) * mk;
        sW1[tid] = w1;
        sW2[tid] = w2;
    }
    float ws1 = w1, ws2 = w2;
    bred2(ws1, ws2, sm, 1);

    if (tid == 0)
        *(float4*)(g_pm + bid * 4) = make_float4(m1, m2, ws1, ws2);
    __syncthreads();

    // ---- Phase B: weighted v accumulation ----
    float4 A1 = make_float4(0.f, 0.f, 0.f, 0.f);
    float4 A2 = make_float4(0.f, 0.f, 0.f, 0.f);
#pragma unroll 4
    for (int i = 0; i < TC; i++) {
        int t = t0 + i;
        float4 xa = __ldcs(((const float4*)v1) + (size_t)(t * BB + b) * (CC / 4) + tid);
        float4 xb = __ldcs(((const float4*)v2) + (size_t)(t * BB + b) * (CC / 4) + tid);
        float u1 = sW1[i];
        float u2 = sW2[i];
        A1.x = fmaf(u1, xa.x, A1.x); A1.y = fmaf(u1, xa.y, A1.y);
        A1.z = fmaf(u1, xa.z, A1.z); A1.w = fmaf(u1, xa.w, A1.w);
        A2.x = fmaf(u2, xb.x, A2.x); A2.y = fmaf(u2, xb.y, A2.y);
        A2.z = fmaf(u2, xb.z, A2.z); A2.w = fmaf(u2, xb.w, A2.w);
    }
    ((float4*)g_pacc1)[(size_t)bid * (CC / 4) + tid] = A1;
    ((float4*)g_pacc2)[(size_t)bid * (CC / 4) + tid] = A2;

    // ---- epilogue: last block of this b performs combine + LayerNorm ----
    __threadfence();                      // publish pacc + pm before counting
    if (tid == 0) {
        int old = atomicAdd(&g_cnt[b], 1);
        s_last = (old == NC - 1);
    }
    __syncthreads();
    if (!s_last) return;

    // chunk weights (warp 0; NC == 16 <= 32 lanes)
    if (warp == 0) {
        float4 pm = make_float4(-3.0e38f, -3.0e38f, 0.f, 0.f);
        if (lane < NC) pm = *(const float4*)(g_pm + (b * NC + lane) * 4);
        float M1 = pm.x, M2 = pm.y;
#pragma unroll
        for (int o = 16; o > 0; o >>= 1) {
            M1 = fmaxf(M1, __shfl_xor_sync(0xffffffffu, M1, o));
            M2 = fmaxf(M2, __shfl_xor_sync(0xffffffffu, M2, o));
        }
        float f1 = 0.f, f2 = 0.f;
        if (lane < NC) {
            f1 = expf(pm.x - M1);
            f2 = expf(pm.y - M2);
            sf1[lane] = f1;
            sf2[lane] = f2;
        }
        float t1 = pm.z * f1, t2 = pm.w * f2;
#pragma unroll
        for (int o = 16; o > 0; o >>= 1) {
            t1 += __shfl_xor_sync(0xffffffffu, t1, o);
            t2 += __shfl_xor_sync(0xffffffffu, t2, o);
        }
        if (lane == 0) { sS[0] = t1; sS[1] = t2; }
    }
    __syncthreads();

    float i1 = 1.f / sS[0];
    float i2 = 1.f / sS[1];

    // thread owns one float4 feature slice; fixed-order chunk sum (deterministic)
    float4 x = make_float4(0.f, 0.f, 0.f, 0.f);
#pragma unroll
    for (int cc = 0; cc < NC; cc++) {
        float g1 = sf1[cc] * i1;
        float g2 = sf2[cc] * i2;
        float4 p1 = __ldcs(((const float4*)g_pacc1) + (size_t)(b * NC + cc) * (CC / 4) + tid);
        float4 p2 = __ldcs(((const float4*)g_pacc2) + (size_t)(b * NC + cc) * (CC / 4) + tid);
        x.x += g1 * p1.x + g2 * p2.x;
        x.y += g1 * p1.y + g2 * p2.y;
        x.z += g1 * p1.z + g2 * p2.z;
        x.w += g1 * p1.w + g2 * p2.w;
    }

    // LayerNorm over the 1024 features of this b
    float sv = x.x + x.y + x.z + x.w;
    float sq = x.x * x.x + x.y * x.y + x.z * x.z + x.w * x.w;
    bred2(sv, sq, sm, 1);
    float mu = sv * (1.f / (float)CC);
    float var = sq * (1.f / (float)CC) - mu * mu;
    float inv = rsqrtf(var + 1e-6f);

    int d = tid * 4;
    float4 g = *(const float4*)(ln_g + d);
    float4 bb = *(const float4*)(ln_b + d);
    float4 o;
    o.x = (x.x - mu) * inv * g.x + bb.x;
    o.y = (x.y - mu) * inv * g.y + bb.y;
    o.z = (x.z - mu) * inv * g.z + bb.z;
    o.w = (x.w - mu) * inv * g.w + bb.w;
    *(float4*)(out + b * CC + d) = o;
}

// ---------------- launch ----------------
extern "C" void kernel_launch(void* const* d_in, const int* in_sizes, int n_in,
                              void* d_out, int out_size) {
    const float* q1     = (const float*)d_in[0];
    const float* k1     = (const float*)d_in[1];
    const float* v1     = (const float*)d_in[2];
    const float* q2     = (const float*)d_in[3];
    const float* k2     = (const float*)d_in[4];
    const float* v2     = (const float*)d_in[5];
    const float* k_mask = (const float*)d_in[6];
    const float* sa_w   = (const float*)d_in[7];
    const float* sa_b   = (const float*)d_in[8];
    const float* a1_w   = (const float*)d_in[9];
    // d_in[10] = a1_b : constant shift, cancels in softmax — unused
    const float* qk_w   = (const float*)d_in[11];
    const float* qk_b   = (const float*)d_in[12];
    const float* ln_g   = (const float*)d_in[13];
    const float* ln_b   = (const float*)d_in[14];
    float* out = (float*)d_out;

    k_rowgemm<<<256, 256>>>(q1, q2, sa_w, qk_w, sa_b, qk_b);
    k_fused<<<BB * NC, 256>>>(k1, k2, v1, v2, a1_w, k_mask, ln_g, ln_b, out);
}